// round 1
// baseline (speedup 1.0000x reference)
#include <cuda_runtime.h>

// Problem constants
#define BATCH 2
#define SEQL  4096
#define OUTD  512
#define NHEAD 8
#define DK    64
#define RATE  4
#define NLPAD 4100              // SEQL + RATE (pad = RATE since L % RATE == 0)
#define NSUB  1025              // NLPAD / RATE
#define MROWS (BATCH * NLPAD)   // 8200
#define SCALE 0.125f            // 1/sqrt(64)
#define NEGBIG 1e30f
#define PADW  68                // smem row stride (floats), 16B-aligned rows

// Scratch: Q/K/V in [(b*H+h)*RATE+r][n][64] layout. 3 x 16.8 MB.
__device__ float g_Q[(size_t)BATCH * NHEAD * RATE * NSUB * DK];
__device__ float g_K[(size_t)BATCH * NHEAD * RATE * NSUB * DK];
__device__ float g_V[(size_t)BATCH * NHEAD * RATE * NSUB * DK];

// ---------------------------------------------------------------------------
// Fused projection: [Q,K,V] = xpad @ [Wq,Wk,Wv], written in permuted layout.
// Pad rows (t >= SEQL) read x as zero -> projections are exactly zero there
// (needed: key i=1024 contributes exp(0) to every softmax denominator).
// ---------------------------------------------------------------------------
__global__ __launch_bounds__(256) void proj_kernel(
    const float* __restrict__ x,
    const float* __restrict__ Wq,
    const float* __restrict__ Wk,
    const float* __restrict__ Wv)
{
    __shared__ float Xs[64][17];
    __shared__ float Wqs[16][64];
    __shared__ float Wks[16][64];
    __shared__ float Wvs[16][64];

    const int tid = threadIdx.x;
    const int ty = tid >> 4, tx = tid & 15;
    const int row0 = blockIdx.x * 64;
    const int col0 = blockIdx.y * 64;

    float aQ[4][4] = {}, aK[4][4] = {}, aV[4][4] = {};

    for (int k0 = 0; k0 < OUTD; k0 += 16) {
        __syncthreads();
        // X tile 64x16 (zero for pad rows / OOB rows)
        #pragma unroll
        for (int it = 0; it < 4; it++) {
            int id = tid + it * 256;
            int rr = id >> 4, cc = id & 15;
            int m = row0 + rr;
            float v = 0.f;
            if (m < MROWS) {
                int b = m / NLPAD;
                int t = m - b * NLPAD;
                if (t < SEQL) v = x[((size_t)(b * SEQL + t)) * OUTD + k0 + cc];
            }
            Xs[rr][cc] = v;
        }
        // W tiles 16x64 each
        #pragma unroll
        for (int it = 0; it < 4; it++) {
            int id = tid + it * 256;
            int rr = id >> 6, cc = id & 63;
            int g = (k0 + rr) * OUTD + col0 + cc;
            Wqs[rr][cc] = Wq[g];
            Wks[rr][cc] = Wk[g];
            Wvs[rr][cc] = Wv[g];
        }
        __syncthreads();

        #pragma unroll
        for (int kk = 0; kk < 16; kk++) {
            float a[4];
            #pragma unroll
            for (int i = 0; i < 4; i++) a[i] = Xs[ty * 4 + i][kk];
            float4 bq = *(const float4*)&Wqs[kk][tx * 4];
            float4 bk = *(const float4*)&Wks[kk][tx * 4];
            float4 bv = *(const float4*)&Wvs[kk][tx * 4];
            #pragma unroll
            for (int i = 0; i < 4; i++) {
                aQ[i][0] += a[i] * bq.x; aQ[i][1] += a[i] * bq.y;
                aQ[i][2] += a[i] * bq.z; aQ[i][3] += a[i] * bq.w;
                aK[i][0] += a[i] * bk.x; aK[i][1] += a[i] * bk.y;
                aK[i][2] += a[i] * bk.z; aK[i][3] += a[i] * bk.w;
                aV[i][0] += a[i] * bv.x; aV[i][1] += a[i] * bv.y;
                aV[i][2] += a[i] * bv.z; aV[i][3] += a[i] * bv.w;
            }
        }
    }

    // Epilogue: scatter into [(b*H+h)*RATE+r][iq][d] layout
    const int h = col0 >> 6;   // 64-wide col tiles align with heads
    #pragma unroll
    for (int i = 0; i < 4; i++) {
        int m = row0 + ty * 4 + i;
        if (m >= MROWS) continue;
        int b = m / NLPAD;
        int t = m - b * NLPAD;
        int iq = t >> 2;
        int r  = t & 3;
        size_t off = ((((size_t)((b * NHEAD + h) * RATE + r)) * NSUB + iq) * DK) + tx * 4;
        #pragma unroll
        for (int j = 0; j < 4; j++) {
            g_Q[off + j] = aQ[i][j];
            g_K[off + j] = aK[i][j];
            g_V[off + j] = aV[i][j];
        }
    }
}

// ---------------------------------------------------------------------------
// Flash attention over the dilated subsequence (1025 keys) + 7 banded local
// logits per query (zero-padded OOR => logit 0, v 0; included in softmax).
// grid = (16 q-tiles of 64, 64 (b,h,r) combos), 256 threads (16x16 of 4x4).
// ---------------------------------------------------------------------------
__global__ __launch_bounds__(256) void attn_kernel(float* __restrict__ out)
{
    extern __shared__ float sm[];
    float (*Qs)[PADW] = (float(*)[PADW])sm;                              // 64 rows
    float (*Ks)[PADW] = (float(*)[PADW])(sm + 64 * PADW);                // 72 rows
    float (*Vs)[PADW] = (float(*)[PADW])(sm + (64 + 72) * PADW);         // 72 rows
    float (*Ps)[PADW] = (float(*)[PADW])(sm + (64 + 72 + 72) * PADW);    // 64 rows

    const int tid = threadIdx.x;
    const int ty = tid >> 4, tx = tid & 15;
    const int combo = blockIdx.y;           // ((b*H)+h)*RATE + r
    const int q0 = blockIdx.x * 64;         // query subsequence index base (<=960)
    const size_t base = (size_t)combo * NSUB * DK;

    // Load Q tile (all 64 queries valid: i <= 1023)
    #pragma unroll
    for (int it = 0; it < 16; it++) {
        int id = tid + it * 256;
        int rr = id >> 6, cc = id & 63;
        Qs[rr][cc] = g_Q[base + (size_t)(q0 + rr) * DK + cc];
    }

    float m_i[4], l_i[4], acc[4][4];
    #pragma unroll
    for (int i = 0; i < 4; i++) {
        m_i[i] = -NEGBIG; l_i[i] = 0.f;
        #pragma unroll
        for (int j = 0; j < 4; j++) acc[i][j] = 0.f;
    }

    // ---- main key loop: 17 tiles cover 1025 keys ----
    for (int kt = 0; kt < 17; kt++) {
        const int ks = kt * 64;
        __syncthreads();
        #pragma unroll
        for (int it = 0; it < 16; it++) {
            int id = tid + it * 256;
            int rr = id >> 6, cc = id & 63;
            int kidx = ks + rr;
            float kv = 0.f, vv = 0.f;
            if (kidx < NSUB) {
                kv = g_K[base + (size_t)kidx * DK + cc];
                vv = g_V[base + (size_t)kidx * DK + cc];
            }
            Ks[rr][cc] = kv;
            Vs[rr][cc] = vv;
        }
        __syncthreads();

        // S = Q K^T (4x4 per thread)
        float s[4][4] = {};
        #pragma unroll 8
        for (int kk = 0; kk < 64; kk++) {
            float a[4], bb[4];
            #pragma unroll
            for (int i = 0; i < 4; i++) a[i] = Qs[ty * 4 + i][kk];
            #pragma unroll
            for (int j = 0; j < 4; j++) bb[j] = Ks[tx * 4 + j][kk];
            #pragma unroll
            for (int i = 0; i < 4; i++)
                #pragma unroll
                for (int j = 0; j < 4; j++)
                    s[i][j] += a[i] * bb[j];
        }

        float rmax[4];
        #pragma unroll
        for (int i = 0; i < 4; i++) {
            rmax[i] = -NEGBIG;
            #pragma unroll
            for (int j = 0; j < 4; j++) {
                int kidx = ks + tx * 4 + j;
                s[i][j] = (kidx < NSUB) ? s[i][j] * SCALE : -NEGBIG;
                rmax[i] = fmaxf(rmax[i], s[i][j]);
            }
        }
        #pragma unroll
        for (int off = 8; off > 0; off >>= 1)
            #pragma unroll
            for (int i = 0; i < 4; i++)
                rmax[i] = fmaxf(rmax[i], __shfl_xor_sync(0xffffffffu, rmax[i], off));

        float alpha[4], rsum[4];
        #pragma unroll
        for (int i = 0; i < 4; i++) {
            float mn = fmaxf(m_i[i], rmax[i]);
            alpha[i] = __expf(m_i[i] - mn);
            m_i[i] = mn;
            float rs = 0.f;
            #pragma unroll
            for (int j = 0; j < 4; j++) {
                float p = __expf(s[i][j] - mn);
                s[i][j] = p;
                rs += p;
            }
            rsum[i] = rs;
        }
        #pragma unroll
        for (int off = 8; off > 0; off >>= 1)
            #pragma unroll
            for (int i = 0; i < 4; i++)
                rsum[i] += __shfl_xor_sync(0xffffffffu, rsum[i], off);
        #pragma unroll
        for (int i = 0; i < 4; i++) {
            l_i[i] = l_i[i] * alpha[i] + rsum[i];
            #pragma unroll
            for (int j = 0; j < 4; j++) acc[i][j] *= alpha[i];
        }

        // stage P, then acc += P @ V
        #pragma unroll
        for (int i = 0; i < 4; i++)
            #pragma unroll
            for (int j = 0; j < 4; j++)
                Ps[ty * 4 + i][tx * 4 + j] = s[i][j];
        __syncthreads();
        #pragma unroll 8
        for (int kk = 0; kk < 64; kk++) {
            float4 v4 = *(const float4*)&Vs[kk][tx * 4];
            #pragma unroll
            for (int i = 0; i < 4; i++) {
                float p = Ps[ty * 4 + i][kk];
                acc[i][0] += p * v4.x; acc[i][1] += p * v4.y;
                acc[i][2] += p * v4.z; acc[i][3] += p * v4.w;
            }
        }
    }

    // ---- local tile: 7 banded logits, keys q0-3 .. q0+66 (zero-padded OOR) ----
    __syncthreads();
    for (int it = 0; it < 18; it++) {
        int id = tid + it * 256;
        if (id < 70 * 64) {
            int rr = id >> 6, cc = id & 63;
            int idx = q0 - 3 + rr;
            float kv = 0.f, vv = 0.f;
            if (idx >= 0 && idx < NSUB) {
                kv = g_K[base + (size_t)idx * DK + cc];
                vv = g_V[base + (size_t)idx * DK + cc];
            }
            Ks[rr][cc] = kv;
            Vs[rr][cc] = vv;
        }
    }
    __syncthreads();

    float sl[4];
    if (tx < 7) {
        #pragma unroll
        for (int i = 0; i < 4; i++) sl[i] = 0.f;
        #pragma unroll 8
        for (int kk = 0; kk < 64; kk++) {
            #pragma unroll
            for (int i = 0; i < 4; i++)
                sl[i] += Qs[ty * 4 + i][kk] * Ks[ty * 4 + i + tx][kk];
        }
        #pragma unroll
        for (int i = 0; i < 4; i++) sl[i] *= SCALE;
    } else {
        #pragma unroll
        for (int i = 0; i < 4; i++) sl[i] = -NEGBIG;
    }

    float rmax[4];
    #pragma unroll
    for (int i = 0; i < 4; i++) rmax[i] = sl[i];
    #pragma unroll
    for (int off = 8; off > 0; off >>= 1)
        #pragma unroll
        for (int i = 0; i < 4; i++)
            rmax[i] = fmaxf(rmax[i], __shfl_xor_sync(0xffffffffu, rmax[i], off));

    float alpha[4], pl[4], rsum[4];
    #pragma unroll
    for (int i = 0; i < 4; i++) {
        float mn = fmaxf(m_i[i], rmax[i]);
        alpha[i] = __expf(m_i[i] - mn);
        m_i[i] = mn;
        pl[i] = (tx < 7) ? __expf(sl[i] - mn) : 0.f;
        rsum[i] = pl[i];
    }
    #pragma unroll
    for (int off = 8; off > 0; off >>= 1)
        #pragma unroll
        for (int i = 0; i < 4; i++)
            rsum[i] += __shfl_xor_sync(0xffffffffu, rsum[i], off);
    #pragma unroll
    for (int i = 0; i < 4; i++) {
        l_i[i] = l_i[i] * alpha[i] + rsum[i];
        #pragma unroll
        for (int j = 0; j < 4; j++) acc[i][j] *= alpha[i];
    }

    if (tx < 7) {
        #pragma unroll
        for (int i = 0; i < 4; i++) Ps[ty * 4 + i][tx] = pl[i];
    }
    __syncthreads();

    #pragma unroll
    for (int j = 0; j < 7; j++) {
        #pragma unroll
        for (int i = 0; i < 4; i++) {
            float p = Ps[ty * 4 + i][j];
            float4 v4 = *(const float4*)&Vs[ty * 4 + i + j][tx * 4];
            acc[i][0] += p * v4.x; acc[i][1] += p * v4.y;
            acc[i][2] += p * v4.z; acc[i][3] += p * v4.w;
        }
    }

    // ---- epilogue: normalize, write (all queries here map to t < SEQL) ----
    const int b = combo >> 5;
    const int h = (combo >> 2) & 7;
    const int r = combo & 3;
    #pragma unroll
    for (int i = 0; i < 4; i++) {
        float inv = 1.f / l_i[i];
        int ig = q0 + ty * 4 + i;
        int t = ig * 4 + r;
        size_t o = ((size_t)(b * SEQL + t)) * OUTD + h * 64 + tx * 4;
        #pragma unroll
        for (int j = 0; j < 4; j++) out[o + j] = acc[i][j] * inv;
    }
}

// ---------------------------------------------------------------------------
extern "C" void kernel_launch(void* const* d_in, const int* in_sizes, int n_in,
                              void* d_out, int out_size)
{
    const float* x  = (const float*)d_in[0];
    const float* Wq = (const float*)d_in[1];
    const float* Wk = (const float*)d_in[2];
    const float* Wv = (const float*)d_in[3];
    float* out = (float*)d_out;

    const int smem_bytes = (64 + 72 + 72 + 64) * PADW * (int)sizeof(float); // 73,984
    cudaFuncSetAttribute(attn_kernel, cudaFuncAttributeMaxDynamicSharedMemorySize, smem_bytes);

    dim3 pgrid((MROWS + 63) / 64, OUTD / 64);   // 129 x 8
    proj_kernel<<<pgrid, 256>>>(x, Wq, Wk, Wv);

    dim3 agrid(16, BATCH * NHEAD * RATE);       // 16 q-tiles x 64 combos
    attn_kernel<<<agrid, 256, smem_bytes>>>(out);
}

// round 2
// speedup vs baseline: 1.3722x; 1.3722x over previous
#include <cuda_runtime.h>
#include <cstdint>

// Problem constants
#define BATCH 2
#define SEQL  4096
#define OUTD  512
#define NHEAD 8
#define DK    64
#define RATE  4
#define NLPAD 4100              // SEQL + RATE
#define NSUB  1025              // NLPAD / RATE
#define NSUBP 1088              // padded to 17*64 so staging never needs bounds checks
#define MROWS (BATCH * NLPAD)   // 8200
#define NCOMBO (BATCH * NHEAD * RATE)  // 64
#define SCALE 0.125f
#define NEGBIG 1e30f
#define SW    68                // smem row stride (floats), 16B-aligned rows

// Scratch (zero-initialized device globals; pad regions are never written and stay 0).
__device__ float g_Q[(size_t)NCOMBO * NSUBP * DK];  // [combo][iq][d]   row-major
__device__ float g_K[(size_t)NCOMBO * DK * NSUBP];  // [combo][d][iq]   TRANSPOSED
__device__ float g_V[(size_t)NCOMBO * NSUBP * DK];  // [combo][iq][d]   row-major

__device__ __forceinline__ void cpasync16(uint32_t s_addr, const float* g) {
    asm volatile("cp.async.cg.shared.global [%0], [%1], 16;\n" :: "r"(s_addr), "l"(g));
}
__device__ __forceinline__ void cpasync_commit() {
    asm volatile("cp.async.commit_group;\n");
}
__device__ __forceinline__ void cpasync_wait0() {
    asm volatile("cp.async.wait_group 0;\n");
}

// ---------------------------------------------------------------------------
// Fused projection. Pad tokens (t >= SEQL) produce exactly-zero rows.
// ---------------------------------------------------------------------------
__global__ __launch_bounds__(256) void proj_kernel(
    const float* __restrict__ x,
    const float* __restrict__ Wq,
    const float* __restrict__ Wk,
    const float* __restrict__ Wv)
{
    __shared__ float Xs[64][17];
    __shared__ float Wqs[16][64];
    __shared__ float Wks[16][64];
    __shared__ float Wvs[16][64];

    const int tid = threadIdx.x;
    const int ty = tid >> 4, tx = tid & 15;
    const int row0 = blockIdx.x * 64;
    const int col0 = blockIdx.y * 64;

    float aQ[4][4] = {}, aK[4][4] = {}, aV[4][4] = {};

    for (int k0 = 0; k0 < OUTD; k0 += 16) {
        __syncthreads();
        #pragma unroll
        for (int it = 0; it < 4; it++) {
            int id = tid + it * 256;
            int rr = id >> 4, cc = id & 15;
            int m = row0 + rr;
            float v = 0.f;
            if (m < MROWS) {
                int b = m / NLPAD;
                int t = m - b * NLPAD;
                if (t < SEQL) v = x[((size_t)(b * SEQL + t)) * OUTD + k0 + cc];
            }
            Xs[rr][cc] = v;
        }
        #pragma unroll
        for (int it = 0; it < 4; it++) {
            int id = tid + it * 256;
            int rr = id >> 6, cc = id & 63;
            int g = (k0 + rr) * OUTD + col0 + cc;
            Wqs[rr][cc] = Wq[g];
            Wks[rr][cc] = Wk[g];
            Wvs[rr][cc] = Wv[g];
        }
        __syncthreads();

        #pragma unroll
        for (int kk = 0; kk < 16; kk++) {
            float a[4];
            #pragma unroll
            for (int i = 0; i < 4; i++) a[i] = Xs[ty * 4 + i][kk];
            float4 bq = *(const float4*)&Wqs[kk][tx * 4];
            float4 bk = *(const float4*)&Wks[kk][tx * 4];
            float4 bv = *(const float4*)&Wvs[kk][tx * 4];
            #pragma unroll
            for (int i = 0; i < 4; i++) {
                aQ[i][0] += a[i] * bq.x; aQ[i][1] += a[i] * bq.y;
                aQ[i][2] += a[i] * bq.z; aQ[i][3] += a[i] * bq.w;
                aK[i][0] += a[i] * bk.x; aK[i][1] += a[i] * bk.y;
                aK[i][2] += a[i] * bk.z; aK[i][3] += a[i] * bk.w;
                aV[i][0] += a[i] * bv.x; aV[i][1] += a[i] * bv.y;
                aV[i][2] += a[i] * bv.z; aV[i][3] += a[i] * bv.w;
            }
        }
    }

    // Epilogue: Q,V row-major [combo][iq][d]; K transposed [combo][d][iq].
    const int h = col0 >> 6;
    #pragma unroll
    for (int i = 0; i < 4; i++) {
        int m = row0 + ty * 4 + i;
        if (m >= MROWS) continue;
        int b = m / NLPAD;
        int t = m - b * NLPAD;
        int iq = t >> 2;
        int r  = t & 3;
        int combo = (b * NHEAD + h) * RATE + r;
        size_t qv = ((size_t)combo * NSUBP + iq) * DK + tx * 4;
        #pragma unroll
        for (int j = 0; j < 4; j++) {
            g_Q[qv + j] = aQ[i][j];
            g_V[qv + j] = aV[i][j];
        }
        size_t kb = (size_t)combo * DK * NSUBP + iq;
        #pragma unroll
        for (int j = 0; j < 4; j++)
            g_K[kb + (size_t)(tx * 4 + j) * NSUBP] = aK[i][j];
    }
}

// ---------------------------------------------------------------------------
// Flash attention: 17 tiles of 64 dilated keys + 7-wide banded local logits.
// smem: QsT[64][SW] | KsT 2x[64][SW] | Vs 2x[64][SW] | Ps[64][SW]
// ---------------------------------------------------------------------------
__global__ __launch_bounds__(256) void attn_kernel(float* __restrict__ out)
{
    extern __shared__ float sm[];
    float* QsT = sm;                 // QsT[d][q]
    float* Ks0 = sm + 64 * SW;       // 2 buffers, KsT[d][key]
    float* Vs0 = sm + 3 * 64 * SW;   // 2 buffers, Vs[key][d]
    float* Ps  = sm + 5 * 64 * SW;   // Ps[q][key]

    const int tid = threadIdx.x;
    const int ty = tid >> 4, tx = tid & 15;
    const int combo = blockIdx.y;
    const int q0 = blockIdx.x * 64;
    const size_t qbase = (size_t)combo * NSUBP * DK;
    const size_t vbase = (size_t)combo * NSUBP * DK;
    const size_t kbase = (size_t)combo * DK * NSUBP;

    const uint32_t smem_u32 = (uint32_t)__cvta_generic_to_shared(sm);

    // ---- Q: coalesced gmem float4 read, transposed scalar smem store (one-time) ----
    #pragma unroll
    for (int it = 0; it < 4; it++) {
        int id = tid + it * 256;
        int q = id >> 4, seg = id & 15;
        float4 v = *(const float4*)(g_Q + qbase + (size_t)(q0 + q) * DK + seg * 4);
        QsT[(seg * 4 + 0) * SW + q] = v.x;
        QsT[(seg * 4 + 1) * SW + q] = v.y;
        QsT[(seg * 4 + 2) * SW + q] = v.z;
        QsT[(seg * 4 + 3) * SW + q] = v.w;
    }

    // ---- stage tile 0 (cp.async) ----
    {
        const int ks = 0;
        float* Kb = Ks0;
        float* Vb = Vs0;
        #pragma unroll
        for (int it = 0; it < 4; it++) {
            int id = tid + it * 256;
            int row = id >> 4, seg = id & 15;
            cpasync16(smem_u32 + (uint32_t)((Kb - sm) + row * SW + seg * 4) * 4,
                      g_K + kbase + (size_t)row * NSUBP + ks + seg * 4);
            cpasync16(smem_u32 + (uint32_t)((Vb - sm) + row * SW + seg * 4) * 4,
                      g_V + vbase + (size_t)(ks + row) * DK + seg * 4);
        }
        cpasync_commit();
    }

    float m_i[4], l_i[4], acc[4][4];
    #pragma unroll
    for (int i = 0; i < 4; i++) {
        m_i[i] = -NEGBIG; l_i[i] = 0.f;
        #pragma unroll
        for (int j = 0; j < 4; j++) acc[i][j] = 0.f;
    }

    // ---- main key loop ----
    for (int kt = 0; kt < 17; kt++) {
        cpasync_wait0();
        __syncthreads();

        float* Kb = Ks0 + (kt & 1) * 64 * SW;
        float* Vb = Vs0 + (kt & 1) * 64 * SW;

        if (kt < 16) {
            const int ks = (kt + 1) * 64;
            float* Kn = Ks0 + ((kt + 1) & 1) * 64 * SW;
            float* Vn = Vs0 + ((kt + 1) & 1) * 64 * SW;
            #pragma unroll
            for (int it = 0; it < 4; it++) {
                int id = tid + it * 256;
                int row = id >> 4, seg = id & 15;
                cpasync16(smem_u32 + (uint32_t)((Kn - sm) + row * SW + seg * 4) * 4,
                          g_K + kbase + (size_t)row * NSUBP + ks + seg * 4);
                cpasync16(smem_u32 + (uint32_t)((Vn - sm) + row * SW + seg * 4) * 4,
                          g_V + vbase + (size_t)(ks + row) * DK + seg * 4);
            }
            cpasync_commit();
        }

        // S = Q K^T : conflict-free float4 reads
        float s[4][4] = {};
        #pragma unroll 16
        for (int kk = 0; kk < 64; kk++) {
            float4 aq = *(const float4*)(QsT + kk * SW + ty * 4);
            float4 bk = *(const float4*)(Kb + kk * SW + tx * 4);
            s[0][0] += aq.x * bk.x; s[0][1] += aq.x * bk.y; s[0][2] += aq.x * bk.z; s[0][3] += aq.x * bk.w;
            s[1][0] += aq.y * bk.x; s[1][1] += aq.y * bk.y; s[1][2] += aq.y * bk.z; s[1][3] += aq.y * bk.w;
            s[2][0] += aq.z * bk.x; s[2][1] += aq.z * bk.y; s[2][2] += aq.z * bk.z; s[2][3] += aq.z * bk.w;
            s[3][0] += aq.w * bk.x; s[3][1] += aq.w * bk.y; s[3][2] += aq.w * bk.z; s[3][3] += aq.w * bk.w;
        }

        const int ks = kt * 64;
        float rmax[4];
        #pragma unroll
        for (int i = 0; i < 4; i++) {
            rmax[i] = -NEGBIG;
            #pragma unroll
            for (int j = 0; j < 4; j++) {
                int kidx = ks + tx * 4 + j;
                s[i][j] = (kidx < NSUB) ? s[i][j] * SCALE : -NEGBIG;
                rmax[i] = fmaxf(rmax[i], s[i][j]);
            }
        }
        #pragma unroll
        for (int off = 8; off > 0; off >>= 1)
            #pragma unroll
            for (int i = 0; i < 4; i++)
                rmax[i] = fmaxf(rmax[i], __shfl_xor_sync(0xffffffffu, rmax[i], off));

        float alpha[4], rsum[4];
        #pragma unroll
        for (int i = 0; i < 4; i++) {
            float mn = fmaxf(m_i[i], rmax[i]);
            alpha[i] = __expf(m_i[i] - mn);
            m_i[i] = mn;
            float rs = 0.f;
            #pragma unroll
            for (int j = 0; j < 4; j++) {
                float p = __expf(s[i][j] - mn);
                s[i][j] = p;
                rs += p;
            }
            rsum[i] = rs;
        }
        #pragma unroll
        for (int off = 8; off > 0; off >>= 1)
            #pragma unroll
            for (int i = 0; i < 4; i++)
                rsum[i] += __shfl_xor_sync(0xffffffffu, rsum[i], off);
        #pragma unroll
        for (int i = 0; i < 4; i++) {
            l_i[i] = l_i[i] * alpha[i] + rsum[i];
            #pragma unroll
            for (int j = 0; j < 4; j++) acc[i][j] *= alpha[i];
        }

        // stage P (float4 stores), then acc += P @ V
        #pragma unroll
        for (int i = 0; i < 4; i++)
            *(float4*)(Ps + (ty * 4 + i) * SW + tx * 4) = make_float4(s[i][0], s[i][1], s[i][2], s[i][3]);
        __syncthreads();

        #pragma unroll 16
        for (int kk = 0; kk < 64; kk++) {
            float4 v4 = *(const float4*)(Vb + kk * SW + tx * 4);
            float p0 = Ps[(ty * 4 + 0) * SW + kk];
            float p1 = Ps[(ty * 4 + 1) * SW + kk];
            float p2 = Ps[(ty * 4 + 2) * SW + kk];
            float p3 = Ps[(ty * 4 + 3) * SW + kk];
            acc[0][0] += p0 * v4.x; acc[0][1] += p0 * v4.y; acc[0][2] += p0 * v4.z; acc[0][3] += p0 * v4.w;
            acc[1][0] += p1 * v4.x; acc[1][1] += p1 * v4.y; acc[1][2] += p1 * v4.z; acc[1][3] += p1 * v4.w;
            acc[2][0] += p2 * v4.x; acc[2][1] += p2 * v4.y; acc[2][2] += p2 * v4.z; acc[2][3] += p2 * v4.w;
            acc[3][0] += p3 * v4.x; acc[3][1] += p3 * v4.y; acc[3][2] += p3 * v4.z; acc[3][3] += p3 * v4.w;
        }
    }

    // ---- local band tile: keys q0-3 .. q0+66 (zeros outside [0,NSUB) -> logit 0) ----
    __syncthreads();
    float (*KsTl)[72] = (float(*)[72])Ks0;   // [d][rr], rr in [0,70)
    float (*Vsl)[SW]  = (float(*)[SW])Vs0;   // [rr][d]
    for (int id = tid; id < 64 * 70; id += 256) {
        int row = id / 70, rr = id - row * 70;
        int idx = q0 - 3 + rr;                       // <= 1026 < NSUBP; pad rows are 0
        KsTl[row][rr] = (idx >= 0) ? g_K[kbase + (size_t)row * NSUBP + idx] : 0.f;
    }
    for (int id = tid; id < 70 * 64; id += 256) {
        int rr = id >> 6, cc = id & 63;
        int idx = q0 - 3 + rr;
        Vsl[rr][cc] = (idx >= 0) ? g_V[vbase + (size_t)idx * DK + cc] : 0.f;
    }
    __syncthreads();

    float sl[4];
    if (tx < 7) {
        #pragma unroll
        for (int i = 0; i < 4; i++) sl[i] = 0.f;
        #pragma unroll 8
        for (int kk = 0; kk < 64; kk++) {
            #pragma unroll
            for (int i = 0; i < 4; i++)
                sl[i] += QsT[kk * SW + ty * 4 + i] * KsTl[kk][ty * 4 + i + tx];
        }
        #pragma unroll
        for (int i = 0; i < 4; i++) sl[i] *= SCALE;
    } else {
        #pragma unroll
        for (int i = 0; i < 4; i++) sl[i] = -NEGBIG;
    }

    float rmax[4];
    #pragma unroll
    for (int i = 0; i < 4; i++) rmax[i] = sl[i];
    #pragma unroll
    for (int off = 8; off > 0; off >>= 1)
        #pragma unroll
        for (int i = 0; i < 4; i++)
            rmax[i] = fmaxf(rmax[i], __shfl_xor_sync(0xffffffffu, rmax[i], off));

    float alpha[4], pl[4], rsum[4];
    #pragma unroll
    for (int i = 0; i < 4; i++) {
        float mn = fmaxf(m_i[i], rmax[i]);
        alpha[i] = __expf(m_i[i] - mn);
        m_i[i] = mn;
        pl[i] = (tx < 7) ? __expf(sl[i] - mn) : 0.f;
        rsum[i] = pl[i];
    }
    #pragma unroll
    for (int off = 8; off > 0; off >>= 1)
        #pragma unroll
        for (int i = 0; i < 4; i++)
            rsum[i] += __shfl_xor_sync(0xffffffffu, rsum[i], off);
    #pragma unroll
    for (int i = 0; i < 4; i++) {
        l_i[i] = l_i[i] * alpha[i] + rsum[i];
        #pragma unroll
        for (int j = 0; j < 4; j++) acc[i][j] *= alpha[i];
    }

    if (tx < 7) {
        #pragma unroll
        for (int i = 0; i < 4; i++) Ps[(ty * 4 + i) * SW + tx] = pl[i];
    }
    __syncthreads();

    #pragma unroll
    for (int j = 0; j < 7; j++) {
        #pragma unroll
        for (int i = 0; i < 4; i++) {
            float p = Ps[(ty * 4 + i) * SW + j];
            float4 v4 = *(const float4*)&Vsl[ty * 4 + i + j][tx * 4];
            acc[i][0] += p * v4.x; acc[i][1] += p * v4.y;
            acc[i][2] += p * v4.z; acc[i][3] += p * v4.w;
        }
    }

    // ---- epilogue ----
    const int b = combo >> 5;
    const int h = (combo >> 2) & 7;
    const int r = combo & 3;
    #pragma unroll
    for (int i = 0; i < 4; i++) {
        float inv = 1.f / l_i[i];
        int ig = q0 + ty * 4 + i;
        int t = ig * 4 + r;
        size_t o = ((size_t)(b * SEQL + t)) * OUTD + h * 64 + tx * 4;
        *(float4*)(out + o) = make_float4(acc[i][0] * inv, acc[i][1] * inv,
                                          acc[i][2] * inv, acc[i][3] * inv);
    }
}

// ---------------------------------------------------------------------------
extern "C" void kernel_launch(void* const* d_in, const int* in_sizes, int n_in,
                              void* d_out, int out_size)
{
    const float* x  = (const float*)d_in[0];
    const float* Wq = (const float*)d_in[1];
    const float* Wk = (const float*)d_in[2];
    const float* Wv = (const float*)d_in[3];
    float* out = (float*)d_out;

    const int smem_bytes = 6 * 64 * SW * (int)sizeof(float); // 104,448 B
    cudaFuncSetAttribute(attn_kernel, cudaFuncAttributeMaxDynamicSharedMemorySize, smem_bytes);

    dim3 pgrid((MROWS + 63) / 64, OUTD / 64);   // 129 x 8
    proj_kernel<<<pgrid, 256>>>(x, Wq, Wk, Wv);

    dim3 agrid(16, NCOMBO);                     // 16 q-tiles x 64 combos
    attn_kernel<<<agrid, 256, smem_bytes>>>(out);
}

// round 3
// speedup vs baseline: 1.4469x; 1.0545x over previous
#include <cuda_runtime.h>
#include <cstdint>

// Problem constants
#define BATCH 2
#define SEQL  4096
#define OUTD  512
#define NHEAD 8
#define DK    64
#define RATE  4
#define NLPAD 4100
#define NSUB  1025
#define NSUBP 1088              // padded to 17*64
#define MROWS (BATCH * NLPAD)   // 8200
#define NCOMBO (BATCH * NHEAD * RATE)  // 64
#define SCALE 0.125f
#define NEGBIG 1e30f

#define BQ   128                // queries per block
#define SWQ  132                // QsT stride (q dim), 16B-aligned rows
#define SWK  68
#define SWV  68
#define SWP  68
#define SWBK 136                // band K stride

// smem offsets (floats)
#define OFF_Q 0
#define OFF_K (OFF_Q + 64 * SWQ)            // 8448
#define OFF_P (OFF_K + 2 * 64 * SWK)        // 17152
#define OFF_V (OFF_P + BQ * SWP)            // 25856
#define SMEM_FLOATS (OFF_V + 134 * SWV + 16)  // band V needs 134*68
// main V usage: 2*64*68 = 8704 (< 9112+16 reserved)

typedef unsigned long long ull;

__device__ float g_Q[(size_t)NCOMBO * NSUBP * DK];  // [combo][iq][d]
__device__ float g_K[(size_t)NCOMBO * DK * NSUBP];  // [combo][d][iq] transposed
__device__ float g_V[(size_t)NCOMBO * NSUBP * DK];  // [combo][iq][d]

__device__ __forceinline__ ull pack2(float a, float b) {
    ull r; asm("mov.b64 %0, {%1, %2};" : "=l"(r) : "f"(a), "f"(b)); return r;
}
__device__ __forceinline__ void fma2(ull& d, ull a, ull b) {
    asm("fma.rn.f32x2 %0, %1, %2, %0;" : "+l"(d) : "l"(a), "l"(b));
}
__device__ __forceinline__ void mul2(ull& d, ull a, ull b) {
    asm("mul.rn.f32x2 %0, %1, %2;" : "=l"(d) : "l"(a), "l"(b));
}
__device__ __forceinline__ float2 unpk2(ull v) {
    float2 f; asm("mov.b64 {%0, %1}, %2;" : "=f"(f.x), "=f"(f.y) : "l"(v)); return f;
}
__device__ __forceinline__ void cpasync16(uint32_t s_addr, const float* g) {
    asm volatile("cp.async.cg.shared.global [%0], [%1], 16;\n" :: "r"(s_addr), "l"(g));
}
__device__ __forceinline__ void cpasync_commit() { asm volatile("cp.async.commit_group;\n"); }
__device__ __forceinline__ void cpasync_wait0()  { asm volatile("cp.async.wait_group 0;\n"); }

// ---------------------------------------------------------------------------
// Fused projection with packed f32x2 FMA (dv pairs).
// ---------------------------------------------------------------------------
__global__ __launch_bounds__(256) void proj_kernel(
    const float* __restrict__ x,
    const float* __restrict__ Wq,
    const float* __restrict__ Wk,
    const float* __restrict__ Wv)
{
    __shared__ __align__(16) float Xs[64][17];
    __shared__ __align__(16) float Wqs[16][64];
    __shared__ __align__(16) float Wks[16][64];
    __shared__ __align__(16) float Wvs[16][64];

    const int tid = threadIdx.x;
    const int ty = tid >> 4, tx = tid & 15;
    const int row0 = blockIdx.x * 64;
    const int col0 = blockIdx.y * 64;

    ull aQ[4][2] = {}, aK[4][2] = {}, aV[4][2] = {};

    for (int k0 = 0; k0 < OUTD; k0 += 16) {
        __syncthreads();
        #pragma unroll
        for (int it = 0; it < 4; it++) {
            int id = tid + it * 256;
            int rr = id >> 4, cc = id & 15;
            int m = row0 + rr;
            float v = 0.f;
            if (m < MROWS) {
                int b = m / NLPAD;
                int t = m - b * NLPAD;
                if (t < SEQL) v = x[((size_t)(b * SEQL + t)) * OUTD + k0 + cc];
            }
            Xs[rr][cc] = v;
        }
        #pragma unroll
        for (int it = 0; it < 4; it++) {
            int id = tid + it * 256;
            int rr = id >> 6, cc = id & 63;
            int g = (k0 + rr) * OUTD + col0 + cc;
            Wqs[rr][cc] = Wq[g];
            Wks[rr][cc] = Wk[g];
            Wvs[rr][cc] = Wv[g];
        }
        __syncthreads();

        #pragma unroll
        for (int kk = 0; kk < 16; kk++) {
            ull ad[4];
            #pragma unroll
            for (int i = 0; i < 4; i++) { float a = Xs[ty * 4 + i][kk]; ad[i] = pack2(a, a); }
            ulonglong2 bq = *(const ulonglong2*)&Wqs[kk][tx * 4];
            ulonglong2 bk = *(const ulonglong2*)&Wks[kk][tx * 4];
            ulonglong2 bv = *(const ulonglong2*)&Wvs[kk][tx * 4];
            #pragma unroll
            for (int i = 0; i < 4; i++) {
                fma2(aQ[i][0], ad[i], bq.x); fma2(aQ[i][1], ad[i], bq.y);
                fma2(aK[i][0], ad[i], bk.x); fma2(aK[i][1], ad[i], bk.y);
                fma2(aV[i][0], ad[i], bv.x); fma2(aV[i][1], ad[i], bv.y);
            }
        }
    }

    const int h = col0 >> 6;
    #pragma unroll
    for (int i = 0; i < 4; i++) {
        int m = row0 + ty * 4 + i;
        if (m >= MROWS) continue;
        int b = m / NLPAD;
        int t = m - b * NLPAD;
        int iq = t >> 2;
        int r  = t & 3;
        int combo = (b * NHEAD + h) * RATE + r;
        size_t qv = ((size_t)combo * NSUBP + iq) * DK + tx * 4;
        float2 q0 = unpk2(aQ[i][0]), q1 = unpk2(aQ[i][1]);
        float2 v0 = unpk2(aV[i][0]), v1 = unpk2(aV[i][1]);
        *(float4*)(g_Q + qv) = make_float4(q0.x, q0.y, q1.x, q1.y);
        *(float4*)(g_V + qv) = make_float4(v0.x, v0.y, v1.x, v1.y);
        float2 kk0 = unpk2(aK[i][0]), kk1 = unpk2(aK[i][1]);
        size_t kb = (size_t)combo * DK * NSUBP + iq;
        g_K[kb + (size_t)(tx * 4 + 0) * NSUBP] = kk0.x;
        g_K[kb + (size_t)(tx * 4 + 1) * NSUBP] = kk0.y;
        g_K[kb + (size_t)(tx * 4 + 2) * NSUBP] = kk1.x;
        g_K[kb + (size_t)(tx * 4 + 3) * NSUBP] = kk1.y;
    }
}

// ---------------------------------------------------------------------------
// Flash attention: BQ=128 x BK=64 tiles, 8q x 4k per thread, packed f32x2 FMA.
// ---------------------------------------------------------------------------
__global__ __launch_bounds__(256, 1) void attn_kernel(float* __restrict__ out)
{
    extern __shared__ float sm[];
    float* QsT  = sm + OFF_Q;   // [d][q]  (pre-scaled by SCALE)
    float* Kbuf = sm + OFF_K;   // 2 x [d][key]
    float* Ps   = sm + OFF_P;   // [q][key]
    float* Vbuf = sm + OFF_V;   // 2 x [key][dv]

    const int tid = threadIdx.x;
    const int ty = tid >> 4, tx = tid & 15;
    const int combo = blockIdx.y;
    const int q0 = blockIdx.x * BQ;
    const size_t qb = (size_t)combo * NSUBP * DK;
    const size_t vb = qb;
    const size_t kb = (size_t)combo * DK * NSUBP;

    const uint32_t smem_u32 = (uint32_t)__cvta_generic_to_shared(sm);

    // Q: coalesced float4 gmem read, transposed smem store, fold in SCALE
    #pragma unroll
    for (int it = 0; it < 8; it++) {
        int id = tid + it * 256;
        int q = id >> 4, seg = id & 15;
        float4 v = *(const float4*)(g_Q + qb + (size_t)(q0 + q) * DK + seg * 4);
        QsT[(seg * 4 + 0) * SWQ + q] = v.x * SCALE;
        QsT[(seg * 4 + 1) * SWQ + q] = v.y * SCALE;
        QsT[(seg * 4 + 2) * SWQ + q] = v.z * SCALE;
        QsT[(seg * 4 + 3) * SWQ + q] = v.w * SCALE;
    }

    // stage tile 0
    {
        float* Kn = Kbuf; float* Vn = Vbuf;
        #pragma unroll
        for (int it = 0; it < 4; it++) {
            int id = tid + it * 256;
            int row = id >> 4, seg = id & 15;
            cpasync16(smem_u32 + (uint32_t)((Kn - sm) + row * SWK + seg * 4) * 4,
                      g_K + kb + (size_t)row * NSUBP + seg * 4);
            cpasync16(smem_u32 + (uint32_t)((Vn - sm) + row * SWV + seg * 4) * 4,
                      g_V + vb + (size_t)row * DK + seg * 4);
        }
        cpasync_commit();
    }

    float m_i[8], l_i[8];
    ull accp[8][2];
    #pragma unroll
    for (int i = 0; i < 8; i++) {
        m_i[i] = -NEGBIG; l_i[i] = 0.f;
        accp[i][0] = 0ULL; accp[i][1] = 0ULL;
    }

    for (int kt = 0; kt < 17; kt++) {
        cpasync_wait0();
        __syncthreads();

        float* Kb2 = Kbuf + (kt & 1) * 64 * SWK;
        float* Vb2 = Vbuf + (kt & 1) * 64 * SWV;

        if (kt < 16) {
            const int ks = (kt + 1) * 64;
            float* Kn = Kbuf + ((kt + 1) & 1) * 64 * SWK;
            float* Vn = Vbuf + ((kt + 1) & 1) * 64 * SWV;
            #pragma unroll
            for (int it = 0; it < 4; it++) {
                int id = tid + it * 256;
                int row = id >> 4, seg = id & 15;
                cpasync16(smem_u32 + (uint32_t)((Kn - sm) + row * SWK + seg * 4) * 4,
                          g_K + kb + (size_t)row * NSUBP + ks + seg * 4);
                cpasync16(smem_u32 + (uint32_t)((Vn - sm) + row * SWV + seg * 4) * 4,
                          g_V + vb + (size_t)(ks + row) * DK + seg * 4);
            }
            cpasync_commit();
        }

        // ---- S = Q K^T, packed: q-pairs (from ulonglong2) x dup'd keys ----
        ull sp[4][4];
        #pragma unroll
        for (int ip = 0; ip < 4; ip++)
            #pragma unroll
            for (int j = 0; j < 4; j++) sp[ip][j] = 0ULL;

        #pragma unroll 4
        for (int kk = 0; kk < 64; kk++) {
            ulonglong2 qA = *(const ulonglong2*)(QsT + kk * SWQ + ty * 8);
            ulonglong2 qB = *(const ulonglong2*)(QsT + kk * SWQ + ty * 8 + 4);
            float4 kv = *(const float4*)(Kb2 + kk * SWK + tx * 4);
            ull k0 = pack2(kv.x, kv.x), k1 = pack2(kv.y, kv.y);
            ull k2 = pack2(kv.z, kv.z), k3 = pack2(kv.w, kv.w);
            fma2(sp[0][0], qA.x, k0); fma2(sp[0][1], qA.x, k1);
            fma2(sp[0][2], qA.x, k2); fma2(sp[0][3], qA.x, k3);
            fma2(sp[1][0], qA.y, k0); fma2(sp[1][1], qA.y, k1);
            fma2(sp[1][2], qA.y, k2); fma2(sp[1][3], qA.y, k3);
            fma2(sp[2][0], qB.x, k0); fma2(sp[2][1], qB.x, k1);
            fma2(sp[2][2], qB.x, k2); fma2(sp[2][3], qB.x, k3);
            fma2(sp[3][0], qB.y, k0); fma2(sp[3][1], qB.y, k1);
            fma2(sp[3][2], qB.y, k2); fma2(sp[3][3], qB.y, k3);
        }

        // unpack (already scaled via Q)
        float s[8][4];
        #pragma unroll
        for (int ip = 0; ip < 4; ip++)
            #pragma unroll
            for (int j = 0; j < 4; j++) {
                float2 f = unpk2(sp[ip][j]);
                s[2 * ip][j] = f.x; s[2 * ip + 1][j] = f.y;
            }

        const int ks = kt * 64;
        float rmax[8];
        #pragma unroll
        for (int i = 0; i < 8; i++) {
            rmax[i] = -NEGBIG;
            #pragma unroll
            for (int j = 0; j < 4; j++) {
                int kidx = ks + tx * 4 + j;
                if (kidx >= NSUB) s[i][j] = -NEGBIG;
                rmax[i] = fmaxf(rmax[i], s[i][j]);
            }
        }
        #pragma unroll
        for (int off = 8; off > 0; off >>= 1)
            #pragma unroll
            for (int i = 0; i < 8; i++)
                rmax[i] = fmaxf(rmax[i], __shfl_xor_sync(0xffffffffu, rmax[i], off));

        float alpha[8], rsum[8];
        #pragma unroll
        for (int i = 0; i < 8; i++) {
            float mn = fmaxf(m_i[i], rmax[i]);
            alpha[i] = __expf(m_i[i] - mn);
            m_i[i] = mn;
            float rs = 0.f;
            #pragma unroll
            for (int j = 0; j < 4; j++) {
                float p = __expf(s[i][j] - mn);
                s[i][j] = p;
                rs += p;
            }
            rsum[i] = rs;
        }
        #pragma unroll
        for (int off = 8; off > 0; off >>= 1)
            #pragma unroll
            for (int i = 0; i < 8; i++)
                rsum[i] += __shfl_xor_sync(0xffffffffu, rsum[i], off);
        #pragma unroll
        for (int i = 0; i < 8; i++) {
            l_i[i] = l_i[i] * alpha[i] + rsum[i];
            ull ap = pack2(alpha[i], alpha[i]);
            mul2(accp[i][0], accp[i][0], ap);
            mul2(accp[i][1], accp[i][1], ap);
        }

        // stage P
        #pragma unroll
        for (int i = 0; i < 8; i++)
            *(float4*)(Ps + (ty * 8 + i) * SWP + tx * 4) =
                make_float4(s[i][0], s[i][1], s[i][2], s[i][3]);
        __syncthreads();

        // ---- acc += P @ V, packed over dv pairs, float4 P reads ----
        #pragma unroll 2
        for (int c = 0; c < 16; c++) {
            float pa[8][4];
            #pragma unroll
            for (int i = 0; i < 8; i++) {
                float4 p4 = *(const float4*)(Ps + (ty * 8 + i) * SWP + c * 4);
                pa[i][0] = p4.x; pa[i][1] = p4.y; pa[i][2] = p4.z; pa[i][3] = p4.w;
            }
            #pragma unroll
            for (int u = 0; u < 4; u++) {
                ulonglong2 vp = *(const ulonglong2*)(Vb2 + (c * 4 + u) * SWV + tx * 4);
                #pragma unroll
                for (int i = 0; i < 8; i++) {
                    ull pd = pack2(pa[i][u], pa[i][u]);
                    fma2(accp[i][0], pd, vp.x);
                    fma2(accp[i][1], pd, vp.y);
                }
            }
        }
    }

    // ---- local band: 7 logits per query, keys q-3..q+3 (zero-padded OOR) ----
    __syncthreads();
    float* KsTl = sm + OFF_K;   // [d][rr] stride SWBK, rr in [0,134)
    float* Vsl  = sm + OFF_V;   // [rr][dv] stride SWV, 134 rows
    for (int idx = tid; idx < 64 * SWBK; idx += 256) {
        int row = idx / SWBK, rr = idx - row * SWBK;
        if (rr < 134) {
            int g = q0 - 3 + rr;    // < NSUBP always; g_K zero beyond NSUB
            KsTl[row * SWBK + rr] = (g >= 0) ? g_K[kb + (size_t)row * NSUBP + g] : 0.f;
        }
    }
    for (int idx = tid; idx < 134 * 64; idx += 256) {
        int rr = idx >> 6, cc = idx & 63;
        int g = q0 - 3 + rr;
        Vsl[rr * SWV + cc] = (g >= 0) ? g_V[vb + (size_t)g * DK + cc] : 0.f;
    }
    __syncthreads();

    float sl[8];
    if (tx < 7) {
        #pragma unroll
        for (int i = 0; i < 8; i++) sl[i] = 0.f;
        #pragma unroll 8
        for (int kk = 0; kk < 64; kk++) {
            #pragma unroll
            for (int i = 0; i < 8; i++)
                sl[i] += QsT[kk * SWQ + ty * 8 + i] * KsTl[kk * SWBK + ty * 8 + i + tx];
        }
    } else {
        #pragma unroll
        for (int i = 0; i < 8; i++) sl[i] = -NEGBIG;
    }

    float rmax[8];
    #pragma unroll
    for (int i = 0; i < 8; i++) rmax[i] = sl[i];
    #pragma unroll
    for (int off = 8; off > 0; off >>= 1)
        #pragma unroll
        for (int i = 0; i < 8; i++)
            rmax[i] = fmaxf(rmax[i], __shfl_xor_sync(0xffffffffu, rmax[i], off));

    float alpha[8], pl[8], rsum[8];
    #pragma unroll
    for (int i = 0; i < 8; i++) {
        float mn = fmaxf(m_i[i], rmax[i]);
        alpha[i] = __expf(m_i[i] - mn);
        m_i[i] = mn;
        pl[i] = (tx < 7) ? __expf(sl[i] - mn) : 0.f;
        rsum[i] = pl[i];
    }
    #pragma unroll
    for (int off = 8; off > 0; off >>= 1)
        #pragma unroll
        for (int i = 0; i < 8; i++)
            rsum[i] += __shfl_xor_sync(0xffffffffu, rsum[i], off);
    #pragma unroll
    for (int i = 0; i < 8; i++) {
        l_i[i] = l_i[i] * alpha[i] + rsum[i];
        ull ap = pack2(alpha[i], alpha[i]);
        mul2(accp[i][0], accp[i][0], ap);
        mul2(accp[i][1], accp[i][1], ap);
    }

    if (tx < 7) {
        #pragma unroll
        for (int i = 0; i < 8; i++) Ps[(ty * 8 + i) * SWP + tx] = pl[i];
    }
    __syncthreads();

    #pragma unroll
    for (int j = 0; j < 7; j++) {
        #pragma unroll
        for (int i = 0; i < 8; i++) {
            float p = Ps[(ty * 8 + i) * SWP + j];
            ulonglong2 vp = *(const ulonglong2*)(Vsl + (ty * 8 + i + j) * SWV + tx * 4);
            ull pd = pack2(p, p);
            fma2(accp[i][0], pd, vp.x);
            fma2(accp[i][1], pd, vp.y);
        }
    }

    // ---- epilogue ----
    const int b = combo >> 5;
    const int h = (combo >> 2) & 7;
    const int r = combo & 3;
    #pragma unroll
    for (int i = 0; i < 8; i++) {
        float inv = 1.f / l_i[i];
        int ig = q0 + ty * 8 + i;
        int t = ig * 4 + r;
        float2 a0 = unpk2(accp[i][0]), a1 = unpk2(accp[i][1]);
        size_t o = ((size_t)(b * SEQL + t)) * OUTD + h * 64 + tx * 4;
        *(float4*)(out + o) = make_float4(a0.x * inv, a0.y * inv, a1.x * inv, a1.y * inv);
    }
}

// ---------------------------------------------------------------------------
extern "C" void kernel_launch(void* const* d_in, const int* in_sizes, int n_in,
                              void* d_out, int out_size)
{
    const float* x  = (const float*)d_in[0];
    const float* Wq = (const float*)d_in[1];
    const float* Wk = (const float*)d_in[2];
    const float* Wv = (const float*)d_in[3];
    float* out = (float*)d_out;

    const int smem_bytes = SMEM_FLOATS * (int)sizeof(float); // ~140 KB
    cudaFuncSetAttribute(attn_kernel, cudaFuncAttributeMaxDynamicSharedMemorySize, smem_bytes);

    dim3 pgrid((MROWS + 63) / 64, OUTD / 64);   // 129 x 8
    proj_kernel<<<pgrid, 256>>>(x, Wq, Wk, Wv);

    dim3 agrid(SEQL / RATE / BQ, NCOMBO);       // 8 x 64
    attn_kernel<<<agrid, 256, smem_bytes>>>(out);
}

// round 4
// speedup vs baseline: 1.9280x; 1.3325x over previous
#include <cuda_runtime.h>
#include <cuda_bf16.h>
#include <cstdint>

#define BATCH 2
#define SEQL  4096
#define OUTD  512
#define NHEAD 8
#define RATE  4
#define NLPAD 4100
#define NSUB  1025
#define NSUBP 1088
#define MROWS (BATCH * NLPAD)          // 8200
#define NCOMBO 64
#define SCALE 0.125f
#define NEGBIG 1e30f

#define BQ 128
#define SK 72                          // bf16 smem row stride (144B)
#define BSW 68                         // band fp32 stride

typedef unsigned long long ull;
typedef __nv_bfloat16 bf16;

// gmem scratch (zero-initialized; pad keys 1025..1087 stay zero)
__device__ bf16 g_Qh[(size_t)NCOMBO * NSUBP * 64];
__device__ bf16 g_Ql[(size_t)NCOMBO * NSUBP * 64];
__device__ bf16 g_Kh[(size_t)NCOMBO * NSUBP * 64];
__device__ bf16 g_Kl[(size_t)NCOMBO * NSUBP * 64];
__device__ bf16 g_VTh[(size_t)NCOMBO * 64 * NSUBP];   // [combo][d][key]
__device__ bf16 g_VTl[(size_t)NCOMBO * 64 * NSUBP];
__device__ float g_Vf[(size_t)NCOMBO * NSUBP * 64];   // fp32 V [key][d] for band

__device__ __forceinline__ ull pack2(float a, float b) {
    ull r; asm("mov.b64 %0, {%1, %2};" : "=l"(r) : "f"(a), "f"(b)); return r;
}
__device__ __forceinline__ void fma2(ull& d, ull a, ull b) {
    asm("fma.rn.f32x2 %0, %1, %2, %0;" : "+l"(d) : "l"(a), "l"(b));
}
__device__ __forceinline__ float2 unpk2(ull v) {
    float2 f; asm("mov.b64 {%0, %1}, %2;" : "=f"(f.x), "=f"(f.y) : "l"(v)); return f;
}
__device__ __forceinline__ uint32_t packbf(float hi, float lo) {
    uint32_t r; asm("cvt.rn.bf16x2.f32 %0, %1, %2;" : "=r"(r) : "f"(hi), "f"(lo)); return r;
}
__device__ __forceinline__ void cpasync16(uint32_t s, const void* g) {
    asm volatile("cp.async.cg.shared.global [%0], [%1], 16;\n" :: "r"(s), "l"(g));
}
__device__ __forceinline__ void cpcommit() { asm volatile("cp.async.commit_group;\n"); }
__device__ __forceinline__ void cpwait0()  { asm volatile("cp.async.wait_group 0;\n"); }
__device__ __forceinline__ void cpwait1()  { asm volatile("cp.async.wait_group 1;\n"); }

__device__ __forceinline__ void mma16816(float* d, const uint32_t* a, uint32_t b0, uint32_t b1) {
    asm volatile("mma.sync.aligned.m16n8k16.row.col.f32.bf16.bf16.f32 "
        "{%0,%1,%2,%3}, {%4,%5,%6,%7}, {%8,%9}, {%0,%1,%2,%3};"
        : "+f"(d[0]), "+f"(d[1]), "+f"(d[2]), "+f"(d[3])
        : "r"(a[0]), "r"(a[1]), "r"(a[2]), "r"(a[3]), "r"(b0), "r"(b1));
}

// ---------------------------------------------------------------------------
// Fused projection (fp32 compute, unchanged core). Epilogue: bf16 hi/lo splits.
// ---------------------------------------------------------------------------
__global__ __launch_bounds__(256) void proj_kernel(
    const float* __restrict__ x, const float* __restrict__ Wq,
    const float* __restrict__ Wk, const float* __restrict__ Wv)
{
    __shared__ __align__(16) float Xs[64][17];
    __shared__ __align__(16) float Wqs[16][64];
    __shared__ __align__(16) float Wks[16][64];
    __shared__ __align__(16) float Wvs[16][64];

    const int tid = threadIdx.x;
    const int ty = tid >> 4, tx = tid & 15;
    const int row0 = blockIdx.x * 64;
    const int col0 = blockIdx.y * 64;

    ull aQ[4][2] = {}, aK[4][2] = {}, aV[4][2] = {};

    for (int k0 = 0; k0 < OUTD; k0 += 16) {
        __syncthreads();
        #pragma unroll
        for (int it = 0; it < 4; it++) {
            int id = tid + it * 256;
            int rr = id >> 4, cc = id & 15;
            int m = row0 + rr;
            float v = 0.f;
            if (m < MROWS) {
                int b = m / NLPAD;
                int t = m - b * NLPAD;
                if (t < SEQL) v = x[((size_t)(b * SEQL + t)) * OUTD + k0 + cc];
            }
            Xs[rr][cc] = v;
        }
        #pragma unroll
        for (int it = 0; it < 4; it++) {
            int id = tid + it * 256;
            int rr = id >> 6, cc = id & 63;
            int g = (k0 + rr) * OUTD + col0 + cc;
            Wqs[rr][cc] = Wq[g]; Wks[rr][cc] = Wk[g]; Wvs[rr][cc] = Wv[g];
        }
        __syncthreads();

        #pragma unroll
        for (int kk = 0; kk < 16; kk++) {
            ull ad[4];
            #pragma unroll
            for (int i = 0; i < 4; i++) { float a = Xs[ty * 4 + i][kk]; ad[i] = pack2(a, a); }
            ulonglong2 bq = *(const ulonglong2*)&Wqs[kk][tx * 4];
            ulonglong2 bk = *(const ulonglong2*)&Wks[kk][tx * 4];
            ulonglong2 bv = *(const ulonglong2*)&Wvs[kk][tx * 4];
            #pragma unroll
            for (int i = 0; i < 4; i++) {
                fma2(aQ[i][0], ad[i], bq.x); fma2(aQ[i][1], ad[i], bq.y);
                fma2(aK[i][0], ad[i], bk.x); fma2(aK[i][1], ad[i], bk.y);
                fma2(aV[i][0], ad[i], bv.x); fma2(aV[i][1], ad[i], bv.y);
            }
        }
    }

    const int h = col0 >> 6;
    #pragma unroll
    for (int i = 0; i < 4; i++) {
        int m = row0 + ty * 4 + i;
        if (m >= MROWS) continue;
        int b = m / NLPAD;
        int t = m - b * NLPAD;
        int iq = t >> 2;
        int r  = t & 3;
        int combo = (b * NHEAD + h) * RATE + r;
        float2 q0 = unpk2(aQ[i][0]), q1 = unpk2(aQ[i][1]);
        float2 k0 = unpk2(aK[i][0]), k1 = unpk2(aK[i][1]);
        float2 v0 = unpk2(aV[i][0]), v1 = unpk2(aV[i][1]);
        float qf[4] = {q0.x, q0.y, q1.x, q1.y};
        float kf[4] = {k0.x, k0.y, k1.x, k1.y};
        float vf[4] = {v0.x, v0.y, v1.x, v1.y};
        size_t o = ((size_t)combo * NSUBP + iq) * 64 + tx * 4;
        #pragma unroll
        for (int j = 0; j < 4; j++) {
            float qs = qf[j] * SCALE;
            bf16 qh = __float2bfloat16(qs);
            g_Qh[o + j] = qh;
            g_Ql[o + j] = __float2bfloat16(qs - __bfloat162float(qh));
            bf16 kh = __float2bfloat16(kf[j]);
            g_Kh[o + j] = kh;
            g_Kl[o + j] = __float2bfloat16(kf[j] - __bfloat162float(kh));
            bf16 vh = __float2bfloat16(vf[j]);
            size_t ot = ((size_t)combo * 64 + tx * 4 + j) * NSUBP + iq;
            g_VTh[ot] = vh;
            g_VTl[ot] = __float2bfloat16(vf[j] - __bfloat162float(vh));
        }
        *(float4*)(g_Vf + o) = make_float4(vf[0], vf[1], vf[2], vf[3]);
    }
}

// ---------------------------------------------------------------------------
// Tensor-core flash attention (bf16 3-split mma.sync), BQ=128, BK=64, 8 warps.
// smem: Qh[128][72] Ql[128][72] | 2 x {Kh,Kl,VTh,VTl}[64][72] (band reuses bufs)
// ---------------------------------------------------------------------------
#define SM_QH 0
#define SM_QL (BQ * SK)                     // elements (bf16)
#define SM_BUF (2 * BQ * SK)                // 18432
#define BUF_SZ (4 * 64 * SK)                // per buffer, bf16 elems (18432)
#define SMEM_BYTES ((SM_BUF + 2 * BUF_SZ) * 2)   // 110592

__global__ __launch_bounds__(256) void attn_kernel(float* __restrict__ out)
{
    extern __shared__ __align__(16) bf16 sm[];
    bf16* QhS = sm + SM_QH;
    bf16* QlS = sm + SM_QL;
    bf16* buf = sm + SM_BUF;

    const int tid = threadIdx.x;
    const int w = tid >> 5, l = tid & 31;
    const int lq = l >> 2;          // quad row
    const int c  = l & 3;           // quad col
    const int combo = blockIdx.y;
    const int q0 = blockIdx.x * BQ;
    const uint32_t smem_u32 = (uint32_t)__cvta_generic_to_shared(sm);

    const size_t gq = (size_t)combo * NSUBP * 64;
    const size_t gvt = (size_t)combo * 64 * NSUBP;

    // ---- stage Q (hi/lo) via cp.async ----
    #pragma unroll
    for (int it = 0; it < 8; it++) {
        int cid = tid + it * 256;            // 0..2047
        int arr = cid >> 10;
        int rem = cid & 1023;
        int row = rem >> 3, seg = rem & 7;
        uint32_t dst = smem_u32 + (uint32_t)(((arr ? SM_QL : SM_QH) + row * SK) * 2 + seg * 16);
        const bf16* src = (arr ? g_Ql : g_Qh) + gq + (size_t)(q0 + row) * 64 + seg * 8;
        cpasync16(dst, src);
    }
    cpcommit();

    // ---- stage tile 0 ----
    {
        const int ks = 0;
        #pragma unroll
        for (int it = 0; it < 8; it++) {
            int cid = tid + it * 256;        // 0..2047
            int arr = cid >> 9;              // 0..3
            int rem = cid & 511;
            int row = rem >> 3, seg = rem & 7;
            uint32_t dst = smem_u32 + (uint32_t)((SM_BUF + arr * 64 * SK + row * SK) * 2 + seg * 16);
            const bf16* src;
            if (arr == 0)      src = g_Kh + gq + (size_t)(ks + row) * 64 + seg * 8;
            else if (arr == 1) src = g_Kl + gq + (size_t)(ks + row) * 64 + seg * 8;
            else if (arr == 2) src = g_VTh + gvt + (size_t)row * NSUBP + ks + seg * 8;
            else               src = g_VTl + gvt + (size_t)row * NSUBP + ks + seg * 8;
            cpasync16(dst, src);
        }
        cpcommit();
    }
    cpwait0();
    __syncthreads();

    // ---- Q fragments (A-frag layout), held in registers ----
    uint32_t qh[4][4], ql[4][4];
    {
        int r0 = w * 16 + lq;
        #pragma unroll
        for (int kc = 0; kc < 4; kc++) {
            int d0 = kc * 16 + c * 2;
            qh[kc][0] = *(const uint32_t*)(QhS + r0 * SK + d0);
            qh[kc][1] = *(const uint32_t*)(QhS + (r0 + 8) * SK + d0);
            qh[kc][2] = *(const uint32_t*)(QhS + r0 * SK + d0 + 8);
            qh[kc][3] = *(const uint32_t*)(QhS + (r0 + 8) * SK + d0 + 8);
            ql[kc][0] = *(const uint32_t*)(QlS + r0 * SK + d0);
            ql[kc][1] = *(const uint32_t*)(QlS + (r0 + 8) * SK + d0);
            ql[kc][2] = *(const uint32_t*)(QlS + r0 * SK + d0 + 8);
            ql[kc][3] = *(const uint32_t*)(QlS + (r0 + 8) * SK + d0 + 8);
        }
    }

    float oacc[8][4];
    #pragma unroll
    for (int j = 0; j < 8; j++)
        #pragma unroll
        for (int t = 0; t < 4; t++) oacc[j][t] = 0.f;
    float m0 = -NEGBIG, m1 = -NEGBIG, l0 = 0.f, l1 = 0.f;

    for (int kt = 0; kt < 17; kt++) {
        __syncthreads();   // all readers of buf[(kt+1)&1]'s previous contents done
        if (kt < 16) {
            const int ks = (kt + 1) * 64;
            const int boff = SM_BUF + ((kt + 1) & 1) * BUF_SZ;
            #pragma unroll
            for (int it = 0; it < 8; it++) {
                int cid = tid + it * 256;
                int arr = cid >> 9;
                int rem = cid & 511;
                int row = rem >> 3, seg = rem & 7;
                uint32_t dst = smem_u32 + (uint32_t)((boff + arr * 64 * SK + row * SK) * 2 + seg * 16);
                const bf16* src;
                if (arr == 0)      src = g_Kh + gq + (size_t)(ks + row) * 64 + seg * 8;
                else if (arr == 1) src = g_Kl + gq + (size_t)(ks + row) * 64 + seg * 8;
                else if (arr == 2) src = g_VTh + gvt + (size_t)row * NSUBP + ks + seg * 8;
                else               src = g_VTl + gvt + (size_t)row * NSUBP + ks + seg * 8;
                cpasync16(dst, src);
            }
            cpcommit();
            cpwait1();
        } else {
            cpwait0();
        }
        __syncthreads();

        const bf16* KhS  = buf + (kt & 1) * BUF_SZ;
        const bf16* KlS  = KhS + 64 * SK;
        const bf16* VThS = KhS + 2 * 64 * SK;
        const bf16* VTlS = KhS + 3 * 64 * SK;

        // ---- S = Q K^T (3-split) ----
        float sacc[8][4];
        #pragma unroll
        for (int j = 0; j < 8; j++)
            #pragma unroll
            for (int t = 0; t < 4; t++) sacc[j][t] = 0.f;

        #pragma unroll
        for (int kc = 0; kc < 4; kc++) {
            #pragma unroll
            for (int j = 0; j < 8; j++) {
                int krow = j * 8 + lq;
                int d0 = kc * 16 + c * 2;
                uint32_t bh0 = *(const uint32_t*)(KhS + krow * SK + d0);
                uint32_t bh1 = *(const uint32_t*)(KhS + krow * SK + d0 + 8);
                uint32_t bl0 = *(const uint32_t*)(KlS + krow * SK + d0);
                uint32_t bl1 = *(const uint32_t*)(KlS + krow * SK + d0 + 8);
                mma16816(sacc[j], qh[kc], bh0, bh1);
                mma16816(sacc[j], ql[kc], bh0, bh1);
                mma16816(sacc[j], qh[kc], bl0, bl1);
            }
        }

        // ---- mask + online softmax (2 rows/thread) ----
        const int ksb = kt * 64;
        float rmx0 = -NEGBIG, rmx1 = -NEGBIG;
        #pragma unroll
        for (int j = 0; j < 8; j++) {
            int k0i = ksb + j * 8 + c * 2;
            if (k0i >= NSUB) sacc[j][0] = -NEGBIG;
            if (k0i + 1 >= NSUB) sacc[j][1] = -NEGBIG;
            if (k0i >= NSUB) sacc[j][2] = -NEGBIG;
            if (k0i + 1 >= NSUB) sacc[j][3] = -NEGBIG;
            rmx0 = fmaxf(rmx0, fmaxf(sacc[j][0], sacc[j][1]));
            rmx1 = fmaxf(rmx1, fmaxf(sacc[j][2], sacc[j][3]));
        }
        rmx0 = fmaxf(rmx0, __shfl_xor_sync(0xffffffffu, rmx0, 1));
        rmx0 = fmaxf(rmx0, __shfl_xor_sync(0xffffffffu, rmx0, 2));
        rmx1 = fmaxf(rmx1, __shfl_xor_sync(0xffffffffu, rmx1, 1));
        rmx1 = fmaxf(rmx1, __shfl_xor_sync(0xffffffffu, rmx1, 2));

        float mn0 = fmaxf(m0, rmx0), mn1 = fmaxf(m1, rmx1);
        float a0 = __expf(m0 - mn0), a1 = __expf(m1 - mn1);
        m0 = mn0; m1 = mn1;
        float s0 = 0.f, s1 = 0.f;
        #pragma unroll
        for (int j = 0; j < 8; j++) {
            sacc[j][0] = __expf(sacc[j][0] - mn0);
            sacc[j][1] = __expf(sacc[j][1] - mn0);
            sacc[j][2] = __expf(sacc[j][2] - mn1);
            sacc[j][3] = __expf(sacc[j][3] - mn1);
            s0 += sacc[j][0] + sacc[j][1];
            s1 += sacc[j][2] + sacc[j][3];
        }
        s0 += __shfl_xor_sync(0xffffffffu, s0, 1);
        s0 += __shfl_xor_sync(0xffffffffu, s0, 2);
        s1 += __shfl_xor_sync(0xffffffffu, s1, 1);
        s1 += __shfl_xor_sync(0xffffffffu, s1, 2);
        l0 = l0 * a0 + s0;
        l1 = l1 * a1 + s1;
        #pragma unroll
        for (int j = 0; j < 8; j++) {
            oacc[j][0] *= a0; oacc[j][1] *= a0;
            oacc[j][2] *= a1; oacc[j][3] *= a1;
        }

        // ---- PV: P (register A-frags, hi/lo) x V (3-split) ----
        #pragma unroll
        for (int kc = 0; kc < 4; kc++) {
            int j0 = 2 * kc, j1 = 2 * kc + 1;
            uint32_t pah[4], pal[4];
            {
                uint32_t h;
                h = packbf(sacc[j0][1], sacc[j0][0]); pah[0] = h;
                pal[0] = packbf(sacc[j0][1] - __uint_as_float(h & 0xffff0000u),
                                sacc[j0][0] - __uint_as_float(h << 16));
                h = packbf(sacc[j0][3], sacc[j0][2]); pah[1] = h;
                pal[1] = packbf(sacc[j0][3] - __uint_as_float(h & 0xffff0000u),
                                sacc[j0][2] - __uint_as_float(h << 16));
                h = packbf(sacc[j1][1], sacc[j1][0]); pah[2] = h;
                pal[2] = packbf(sacc[j1][1] - __uint_as_float(h & 0xffff0000u),
                                sacc[j1][0] - __uint_as_float(h << 16));
                h = packbf(sacc[j1][3], sacc[j1][2]); pah[3] = h;
                pal[3] = packbf(sacc[j1][3] - __uint_as_float(h & 0xffff0000u),
                                sacc[j1][2] - __uint_as_float(h << 16));
            }
            #pragma unroll
            for (int j = 0; j < 8; j++) {
                int dvrow = j * 8 + lq;
                int kk0 = kc * 16 + c * 2;
                uint32_t bh0 = *(const uint32_t*)(VThS + dvrow * SK + kk0);
                uint32_t bh1 = *(const uint32_t*)(VThS + dvrow * SK + kk0 + 8);
                uint32_t bl0 = *(const uint32_t*)(VTlS + dvrow * SK + kk0);
                uint32_t bl1 = *(const uint32_t*)(VTlS + dvrow * SK + kk0 + 8);
                mma16816(oacc[j], pah, bh0, bh1);
                mma16816(oacc[j], pal, bh0, bh1);
                mma16816(oacc[j], pah, bl0, bl1);
            }
        }
    }

    // ---- band pass: 7 logits/query, keys q-3..q+3 (zero outside tokens) ----
    __syncthreads();
    float* Kband = (float*)(buf);             // [134][BSW]
    float* Vband = Kband + 134 * BSW;
    for (int i = tid; i < 134 * 64; i += 256) {
        int rr = i >> 6, d = i & 63;
        int g = q0 - 3 + rr;
        float kv = 0.f, vv = 0.f;
        if (g >= 0) {
            size_t o = gq + (size_t)g * 64 + d;
            kv = __bfloat162float(g_Kh[o]) + __bfloat162float(g_Kl[o]);
            vv = g_Vf[o];
        }
        Kband[rr * BSW + d] = kv;
        Vband[rr * BSW + d] = vv;
    }
    __syncthreads();

    float bl[2][2];
    #pragma unroll
    for (int rh = 0; rh < 2; rh++) {
        int qlcl = w * 16 + lq + 8 * rh;
        int kk0 = c, kk1 = c + 4;
        float acc0 = 0.f, acc1 = 0.f;
        const float* kb0 = Kband + (qlcl + kk0) * BSW;
        const float* kb1 = Kband + (qlcl + kk1) * BSW;
        #pragma unroll 8
        for (int d = 0; d < 64; d++) {
            float qf = __bfloat162float(QhS[qlcl * SK + d]) + __bfloat162float(QlS[qlcl * SK + d]);
            acc0 += qf * kb0[d];
            if (kk1 < 7) acc1 += qf * kb1[d];
        }
        bl[rh][0] = acc0;
        bl[rh][1] = (kk1 < 7) ? acc1 : -NEGBIG;
    }

    {
        float rmx0 = fmaxf(bl[0][0], bl[0][1]);
        float rmx1 = fmaxf(bl[1][0], bl[1][1]);
        rmx0 = fmaxf(rmx0, __shfl_xor_sync(0xffffffffu, rmx0, 1));
        rmx0 = fmaxf(rmx0, __shfl_xor_sync(0xffffffffu, rmx0, 2));
        rmx1 = fmaxf(rmx1, __shfl_xor_sync(0xffffffffu, rmx1, 1));
        rmx1 = fmaxf(rmx1, __shfl_xor_sync(0xffffffffu, rmx1, 2));
        float mn0 = fmaxf(m0, rmx0), mn1 = fmaxf(m1, rmx1);
        float a0 = __expf(m0 - mn0), a1 = __expf(m1 - mn1);
        m0 = mn0; m1 = mn1;
        float p00 = __expf(bl[0][0] - mn0);
        float p01 = (c + 4 < 7) ? __expf(bl[0][1] - mn0) : 0.f;
        float p10 = __expf(bl[1][0] - mn1);
        float p11 = (c + 4 < 7) ? __expf(bl[1][1] - mn1) : 0.f;
        float s0 = p00 + p01, s1 = p10 + p11;
        s0 += __shfl_xor_sync(0xffffffffu, s0, 1);
        s0 += __shfl_xor_sync(0xffffffffu, s0, 2);
        s1 += __shfl_xor_sync(0xffffffffu, s1, 1);
        s1 += __shfl_xor_sync(0xffffffffu, s1, 2);
        l0 = l0 * a0 + s0;
        l1 = l1 * a1 + s1;
        #pragma unroll
        for (int j = 0; j < 8; j++) {
            oacc[j][0] *= a0; oacc[j][1] *= a0;
            oacc[j][2] *= a1; oacc[j][3] *= a1;
        }

        int r0 = w * 16 + lq;
        #pragma unroll
        for (int kk = 0; kk < 7; kk++) {
            int src = (l & ~3) | (kk & 3);
            float pb0 = __shfl_sync(0xffffffffu, (kk < 4) ? p00 : p01, src);
            float pb1 = __shfl_sync(0xffffffffu, (kk < 4) ? p10 : p11, src);
            const float* v0 = Vband + (r0 + kk) * BSW + c * 2;
            const float* v1 = Vband + (r0 + 8 + kk) * BSW + c * 2;
            #pragma unroll
            for (int j = 0; j < 8; j++) {
                float2 a = *(const float2*)(v0 + j * 8);
                float2 bq = *(const float2*)(v1 + j * 8);
                oacc[j][0] += pb0 * a.x; oacc[j][1] += pb0 * a.y;
                oacc[j][2] += pb1 * bq.x; oacc[j][3] += pb1 * bq.y;
            }
        }
    }

    // ---- epilogue ----
    const int b = combo >> 5;
    const int h = (combo >> 2) & 7;
    const int r = combo & 3;
    float inv0 = 1.f / l0, inv1 = 1.f / l1;
    int qg = q0 + w * 16 + lq;
    size_t o0 = ((size_t)(b * SEQL + qg * 4 + r)) * OUTD + h * 64 + c * 2;
    size_t o1 = ((size_t)(b * SEQL + (qg + 8) * 4 + r)) * OUTD + h * 64 + c * 2;
    #pragma unroll
    for (int j = 0; j < 8; j++) {
        *(float2*)(out + o0 + j * 8) = make_float2(oacc[j][0] * inv0, oacc[j][1] * inv0);
        *(float2*)(out + o1 + j * 8) = make_float2(oacc[j][2] * inv1, oacc[j][3] * inv1);
    }
}

// ---------------------------------------------------------------------------
extern "C" void kernel_launch(void* const* d_in, const int* in_sizes, int n_in,
                              void* d_out, int out_size)
{
    const float* x  = (const float*)d_in[0];
    const float* Wq = (const float*)d_in[1];
    const float* Wk = (const float*)d_in[2];
    const float* Wv = (const float*)d_in[3];
    float* out = (float*)d_out;

    cudaFuncSetAttribute(attn_kernel, cudaFuncAttributeMaxDynamicSharedMemorySize, SMEM_BYTES);

    dim3 pgrid((MROWS + 63) / 64, OUTD / 64);   // 129 x 8
    proj_kernel<<<pgrid, 256>>>(x, Wq, Wk, Wv);

    dim3 agrid(SEQL / RATE / BQ, NCOMBO);       // 8 x 64
    attn_kernel<<<agrid, 256, SMEM_BYTES>>>(out);
}

// round 5
// speedup vs baseline: 2.7363x; 1.4193x over previous
#include <cuda_runtime.h>
#include <cuda_bf16.h>
#include <cstdint>

#define BATCH 2
#define SEQL  4096
#define OUTD  512
#define NHEAD 8
#define RATE  4
#define NLPAD 4100
#define NSUB  1025
#define NSUBP 1088
#define NCOMBO 64
#define SCALE 0.125f
#define NEGBIG 1e30f

#define MPB   4160          // padded rows per batch for proj tiling
#define MXP   (2 * MPB)     // 8320 = 65 * 128

#define BQ 128
#define SK 72               // attn bf16 smem stride
#define BSW 68

typedef unsigned long long ull;
typedef __nv_bfloat16 bf16;

// attention scratch (zero-init; pad keys stay zero forever)
__device__ bf16 g_Qh[(size_t)NCOMBO * NSUBP * 64];
__device__ bf16 g_Ql[(size_t)NCOMBO * NSUBP * 64];
__device__ bf16 g_Kh[(size_t)NCOMBO * NSUBP * 64];
__device__ bf16 g_Kl[(size_t)NCOMBO * NSUBP * 64];
__device__ bf16 g_VTh[(size_t)NCOMBO * 64 * NSUBP];
__device__ bf16 g_VTl[(size_t)NCOMBO * 64 * NSUBP];
__device__ float g_Vf[(size_t)NCOMBO * NSUBP * 64];
// projection inputs, bf16 hi/lo (zero-init; pad rows stay zero)
__device__ bf16 g_xh[(size_t)MXP * OUTD];
__device__ bf16 g_xl[(size_t)MXP * OUTD];
__device__ bf16 g_WhT[3][OUTD * OUTD];   // [z][n][k]
__device__ bf16 g_WlT[3][OUTD * OUTD];

__device__ __forceinline__ uint32_t packbf(float hi, float lo) {
    uint32_t r; asm("cvt.rn.bf16x2.f32 %0, %1, %2;" : "=r"(r) : "f"(hi), "f"(lo)); return r;
}
__device__ __forceinline__ void cpasync16(uint32_t s, const void* g) {
    asm volatile("cp.async.cg.shared.global [%0], [%1], 16;\n" :: "r"(s), "l"(g));
}
__device__ __forceinline__ void cpcommit() { asm volatile("cp.async.commit_group;\n"); }
__device__ __forceinline__ void cpwait0()  { asm volatile("cp.async.wait_group 0;\n"); }
__device__ __forceinline__ void cpwait1()  { asm volatile("cp.async.wait_group 1;\n"); }

__device__ __forceinline__ void mma16816(float* d, const uint32_t* a, uint32_t b0, uint32_t b1) {
    asm volatile("mma.sync.aligned.m16n8k16.row.col.f32.bf16.bf16.f32 "
        "{%0,%1,%2,%3}, {%4,%5,%6,%7}, {%8,%9}, {%0,%1,%2,%3};"
        : "+f"(d[0]), "+f"(d[1]), "+f"(d[2]), "+f"(d[3])
        : "r"(a[0]), "r"(a[1]), "r"(a[2]), "r"(a[3]), "r"(b0), "r"(b1));
}

// ---------------------------------------------------------------------------
// Split x into bf16 hi/lo at padded row index m' = b*MPB + t.
// ---------------------------------------------------------------------------
__global__ __launch_bounds__(256) void splitx_kernel(const float* __restrict__ x)
{
    int idx = blockIdx.x * 256 + threadIdx.x;      // float4 index
    int flat = idx * 4;
    int b = flat / (SEQL * OUTD);
    int rem = flat - b * (SEQL * OUTD);
    int t = rem / OUTD;
    int k = rem - t * OUTD;
    float4 v = *(const float4*)(x + (size_t)flat);
    size_t o = ((size_t)(b * MPB + t)) * OUTD + k;
    float hx = __bfloat162float(__float2bfloat16(v.x));
    float hy = __bfloat162float(__float2bfloat16(v.y));
    float hz = __bfloat162float(__float2bfloat16(v.z));
    float hw = __bfloat162float(__float2bfloat16(v.w));
    *(uint2*)(g_xh + o) = make_uint2(packbf(hy, hx), packbf(hw, hz));
    *(uint2*)(g_xl + o) = make_uint2(packbf(v.y - hy, v.x - hx), packbf(v.w - hw, v.z - hz));
}

// ---------------------------------------------------------------------------
// Split + transpose W -> WT[n][k] hi/lo. grid (OUTD, 3).
// ---------------------------------------------------------------------------
__global__ __launch_bounds__(256) void splitw_kernel(
    const float* __restrict__ Wq, const float* __restrict__ Wk, const float* __restrict__ Wv)
{
    int k = blockIdx.x, z = blockIdx.y;
    const float* W = (z == 0) ? Wq : (z == 1) ? Wk : Wv;
    #pragma unroll
    for (int half = 0; half < 2; half++) {
        int n = threadIdx.x + half * 256;
        float v = W[(size_t)k * OUTD + n];
        bf16 h = __float2bfloat16(v);
        g_WhT[z][(size_t)n * OUTD + k] = h;
        g_WlT[z][(size_t)n * OUTD + k] = __float2bfloat16(v - __bfloat162float(h));
    }
}

// ---------------------------------------------------------------------------
// Tensor-core projection: C[128x64] = x[128xK] * W[Kx64] per (mtile, head, z).
// ---------------------------------------------------------------------------
#define KT 32
#define SA 40
#define P_AH 0
#define P_AL (2 * 128 * SA)        // 10240
#define P_BH (4 * 128 * SA)        // 20480
#define P_BL (P_BH + 2 * 64 * SA)  // 25600
#define P_SMEM_ELEMS (P_BL + 2 * 64 * SA)   // 30720 bf16 = 61440 B
#define SC 68

__global__ __launch_bounds__(256, 2) void proj_tc_kernel(float* /*unused*/)
{
    extern __shared__ __align__(16) bf16 psm[];
    const int tid = threadIdx.x;
    const int w = tid >> 5, l = tid & 31;
    const int lq = l >> 2, c = l & 3;
    const int wm = w & 3, wn = w >> 2;
    const int m0 = blockIdx.x * 128;
    const int n0 = blockIdx.y * 64;      // head * 64
    const int z  = blockIdx.z;
    const uint32_t su = (uint32_t)__cvta_generic_to_shared(psm);

    const bf16* WhT = g_WhT[z] + (size_t)n0 * OUTD;
    const bf16* WlT = g_WlT[z] + (size_t)n0 * OUTD;

    // stage k-tile kt into buffer bi
    auto stage = [&](int kt, int bi) {
        const int k0 = kt * KT;
        #pragma unroll
        for (int it = 0; it < 4; it++) {   // A: 1024 transfers of 16B over 4 iters
            int cid = tid + it * 256;
            int sp = cid >> 9, rem = cid & 511;
            int row = rem >> 2, seg = rem & 3;
            uint32_t dst = su + (uint32_t)(((sp ? P_AL : P_AH) + bi * 128 * SA + row * SA + seg * 8) * 2);
            const bf16* src = (sp ? g_xl : g_xh) + (size_t)(m0 + row) * OUTD + k0 + seg * 8;
            cpasync16(dst, src);
        }
        #pragma unroll
        for (int it = 0; it < 2; it++) {   // B: 512 transfers
            int cid = tid + it * 256;
            int sp = cid >> 8, rem = cid & 255;
            int row = rem >> 2, seg = rem & 3;
            uint32_t dst = su + (uint32_t)(((sp ? P_BL : P_BH) + bi * 64 * SA + row * SA + seg * 8) * 2);
            const bf16* src = (sp ? WlT : WhT) + (size_t)row * OUTD + k0 + seg * 8;
            cpasync16(dst, src);
        }
        cpcommit();
    };

    stage(0, 0);

    float acc[2][4][4];
    #pragma unroll
    for (int i = 0; i < 2; i++)
        #pragma unroll
        for (int j = 0; j < 4; j++)
            #pragma unroll
            for (int t = 0; t < 4; t++) acc[i][j][t] = 0.f;

    for (int kt = 0; kt < OUTD / KT; kt++) {
        if (kt < OUTD / KT - 1) { stage(kt + 1, (kt + 1) & 1); cpwait1(); }
        else cpwait0();
        __syncthreads();
        const bf16* Ah = psm + P_AH + (kt & 1) * 128 * SA;
        const bf16* Al = psm + P_AL + (kt & 1) * 128 * SA;
        const bf16* Bh = psm + P_BH + (kt & 1) * 64 * SA;
        const bf16* Bl = psm + P_BL + (kt & 1) * 64 * SA;

        #pragma unroll
        for (int hh = 0; hh < 2; hh++) {
            const int kb = hh * 16;
            uint32_t ah[2][4], al[2][4];
            #pragma unroll
            for (int mb = 0; mb < 2; mb++) {
                int r0 = wm * 32 + mb * 16 + lq;
                ah[mb][0] = *(const uint32_t*)(Ah + r0 * SA + kb + c * 2);
                ah[mb][1] = *(const uint32_t*)(Ah + (r0 + 8) * SA + kb + c * 2);
                ah[mb][2] = *(const uint32_t*)(Ah + r0 * SA + kb + c * 2 + 8);
                ah[mb][3] = *(const uint32_t*)(Ah + (r0 + 8) * SA + kb + c * 2 + 8);
                al[mb][0] = *(const uint32_t*)(Al + r0 * SA + kb + c * 2);
                al[mb][1] = *(const uint32_t*)(Al + (r0 + 8) * SA + kb + c * 2);
                al[mb][2] = *(const uint32_t*)(Al + r0 * SA + kb + c * 2 + 8);
                al[mb][3] = *(const uint32_t*)(Al + (r0 + 8) * SA + kb + c * 2 + 8);
            }
            #pragma unroll
            for (int nb = 0; nb < 4; nb++) {
                int n = wn * 32 + nb * 8 + lq;
                uint32_t bh0 = *(const uint32_t*)(Bh + n * SA + kb + c * 2);
                uint32_t bh1 = *(const uint32_t*)(Bh + n * SA + kb + c * 2 + 8);
                uint32_t bl0 = *(const uint32_t*)(Bl + n * SA + kb + c * 2);
                uint32_t bl1 = *(const uint32_t*)(Bl + n * SA + kb + c * 2 + 8);
                #pragma unroll
                for (int mb = 0; mb < 2; mb++) {
                    mma16816(acc[mb][nb], ah[mb], bh0, bh1);
                    mma16816(acc[mb][nb], al[mb], bh0, bh1);
                    mma16816(acc[mb][nb], ah[mb], bl0, bl1);
                }
            }
        }
        __syncthreads();
    }

    // stage C to smem
    float* C = (float*)psm;
    #pragma unroll
    for (int mb = 0; mb < 2; mb++) {
        int r0 = wm * 32 + mb * 16 + lq;
        #pragma unroll
        for (int nb = 0; nb < 4; nb++) {
            int col = wn * 32 + nb * 8 + c * 2;
            *(float2*)(C + r0 * SC + col)       = make_float2(acc[mb][nb][0], acc[mb][nb][1]);
            *(float2*)(C + (r0 + 8) * SC + col) = make_float2(acc[mb][nb][2], acc[mb][nb][3]);
        }
    }
    __syncthreads();

    // epilogue: 2 threads per row, 32 cols each
    {
        int r = tid >> 1;
        int half = tid & 1;
        int m = m0 + r;
        int b = m / MPB;
        int t = m - b * MPB;
        if (t < SEQL) {
            int iq = t >> 2, r4 = t & 3;
            int h = blockIdx.y;
            int combo = (b * NHEAD + h) * RATE + r4;
            size_t orow = ((size_t)combo * NSUBP + iq) * 64;
            #pragma unroll
            for (int j = 0; j < 8; j++) {
                int d = half * 32 + j * 4;
                float4 v = *(const float4*)(C + r * SC + d);
                float vf[4] = {v.x, v.y, v.z, v.w};
                if (z == 0) {
                    #pragma unroll
                    for (int e = 0; e < 4; e++) vf[e] *= SCALE;
                }
                float h0 = __bfloat162float(__float2bfloat16(vf[0]));
                float h1 = __bfloat162float(__float2bfloat16(vf[1]));
                float h2 = __bfloat162float(__float2bfloat16(vf[2]));
                float h3 = __bfloat162float(__float2bfloat16(vf[3]));
                uint2 uh = make_uint2(packbf(h1, h0), packbf(h3, h2));
                uint2 ul = make_uint2(packbf(vf[1] - h1, vf[0] - h0), packbf(vf[3] - h3, vf[2] - h2));
                if (z == 0) {
                    *(uint2*)(g_Qh + orow + d) = uh;
                    *(uint2*)(g_Ql + orow + d) = ul;
                } else if (z == 1) {
                    *(uint2*)(g_Kh + orow + d) = uh;
                    *(uint2*)(g_Kl + orow + d) = ul;
                } else {
                    *(float4*)(g_Vf + orow + d) = v;
                    float hs[4] = {h0, h1, h2, h3};
                    #pragma unroll
                    for (int e = 0; e < 4; e++) {
                        size_t ot = ((size_t)combo * 64 + d + e) * NSUBP + iq;
                        g_VTh[ot] = __float2bfloat16(hs[e]);
                        g_VTl[ot] = __float2bfloat16(vf[e] - hs[e]);
                    }
                }
            }
        }
    }
}

// ---------------------------------------------------------------------------
// Tensor-core flash attention (unchanged math; 2 CTAs/SM).
// ---------------------------------------------------------------------------
#define SM_QH 0
#define SM_QL (BQ * SK)
#define SM_BUF (2 * BQ * SK)
#define BUF_SZ (4 * 64 * SK)
#define SMEM_BYTES ((SM_BUF + 2 * BUF_SZ) * 2)   // 110592

__global__ __launch_bounds__(256, 2) void attn_kernel(float* __restrict__ out)
{
    extern __shared__ __align__(16) bf16 sm[];
    bf16* QhS = sm + SM_QH;
    bf16* QlS = sm + SM_QL;
    bf16* buf = sm + SM_BUF;

    const int tid = threadIdx.x;
    const int w = tid >> 5, l = tid & 31;
    const int lq = l >> 2;
    const int c  = l & 3;
    const int combo = blockIdx.y;
    const int q0 = blockIdx.x * BQ;
    const uint32_t smem_u32 = (uint32_t)__cvta_generic_to_shared(sm);

    const size_t gq = (size_t)combo * NSUBP * 64;
    const size_t gvt = (size_t)combo * 64 * NSUBP;

    #pragma unroll
    for (int it = 0; it < 8; it++) {
        int cid = tid + it * 256;
        int arr = cid >> 10;
        int rem = cid & 1023;
        int row = rem >> 3, seg = rem & 7;
        uint32_t dst = smem_u32 + (uint32_t)(((arr ? SM_QL : SM_QH) + row * SK) * 2 + seg * 16);
        const bf16* src = (arr ? g_Ql : g_Qh) + gq + (size_t)(q0 + row) * 64 + seg * 8;
        cpasync16(dst, src);
    }
    cpcommit();

    {
        const int ks = 0;
        #pragma unroll
        for (int it = 0; it < 8; it++) {
            int cid = tid + it * 256;
            int arr = cid >> 9;
            int rem = cid & 511;
            int row = rem >> 3, seg = rem & 7;
            uint32_t dst = smem_u32 + (uint32_t)((SM_BUF + arr * 64 * SK + row * SK) * 2 + seg * 16);
            const bf16* src;
            if (arr == 0)      src = g_Kh + gq + (size_t)(ks + row) * 64 + seg * 8;
            else if (arr == 1) src = g_Kl + gq + (size_t)(ks + row) * 64 + seg * 8;
            else if (arr == 2) src = g_VTh + gvt + (size_t)row * NSUBP + ks + seg * 8;
            else               src = g_VTl + gvt + (size_t)row * NSUBP + ks + seg * 8;
            cpasync16(dst, src);
        }
        cpcommit();
    }
    cpwait0();
    __syncthreads();

    uint32_t qh[4][4], ql[4][4];
    {
        int r0 = w * 16 + lq;
        #pragma unroll
        for (int kc = 0; kc < 4; kc++) {
            int d0 = kc * 16 + c * 2;
            qh[kc][0] = *(const uint32_t*)(QhS + r0 * SK + d0);
            qh[kc][1] = *(const uint32_t*)(QhS + (r0 + 8) * SK + d0);
            qh[kc][2] = *(const uint32_t*)(QhS + r0 * SK + d0 + 8);
            qh[kc][3] = *(const uint32_t*)(QhS + (r0 + 8) * SK + d0 + 8);
            ql[kc][0] = *(const uint32_t*)(QlS + r0 * SK + d0);
            ql[kc][1] = *(const uint32_t*)(QlS + (r0 + 8) * SK + d0);
            ql[kc][2] = *(const uint32_t*)(QlS + r0 * SK + d0 + 8);
            ql[kc][3] = *(const uint32_t*)(QlS + (r0 + 8) * SK + d0 + 8);
        }
    }

    float oacc[8][4];
    #pragma unroll
    for (int j = 0; j < 8; j++)
        #pragma unroll
        for (int t = 0; t < 4; t++) oacc[j][t] = 0.f;
    float m0 = -NEGBIG, m1 = -NEGBIG, l0 = 0.f, l1 = 0.f;

    for (int kt = 0; kt < 17; kt++) {
        __syncthreads();
        if (kt < 16) {
            const int ks = (kt + 1) * 64;
            const int boff = SM_BUF + ((kt + 1) & 1) * BUF_SZ;
            #pragma unroll
            for (int it = 0; it < 8; it++) {
                int cid = tid + it * 256;
                int arr = cid >> 9;
                int rem = cid & 511;
                int row = rem >> 3, seg = rem & 7;
                uint32_t dst = smem_u32 + (uint32_t)((boff + arr * 64 * SK + row * SK) * 2 + seg * 16);
                const bf16* src;
                if (arr == 0)      src = g_Kh + gq + (size_t)(ks + row) * 64 + seg * 8;
                else if (arr == 1) src = g_Kl + gq + (size_t)(ks + row) * 64 + seg * 8;
                else if (arr == 2) src = g_VTh + gvt + (size_t)row * NSUBP + ks + seg * 8;
                else               src = g_VTl + gvt + (size_t)row * NSUBP + ks + seg * 8;
                cpasync16(dst, src);
            }
            cpcommit();
            cpwait1();
        } else {
            cpwait0();
        }
        __syncthreads();

        const bf16* KhS  = buf + (kt & 1) * BUF_SZ;
        const bf16* KlS  = KhS + 64 * SK;
        const bf16* VThS = KhS + 2 * 64 * SK;
        const bf16* VTlS = KhS + 3 * 64 * SK;

        float sacc[8][4];
        #pragma unroll
        for (int j = 0; j < 8; j++)
            #pragma unroll
            for (int t = 0; t < 4; t++) sacc[j][t] = 0.f;

        #pragma unroll
        for (int kc = 0; kc < 4; kc++) {
            #pragma unroll
            for (int j = 0; j < 8; j++) {
                int krow = j * 8 + lq;
                int d0 = kc * 16 + c * 2;
                uint32_t bh0 = *(const uint32_t*)(KhS + krow * SK + d0);
                uint32_t bh1 = *(const uint32_t*)(KhS + krow * SK + d0 + 8);
                uint32_t bl0 = *(const uint32_t*)(KlS + krow * SK + d0);
                uint32_t bl1 = *(const uint32_t*)(KlS + krow * SK + d0 + 8);
                mma16816(sacc[j], qh[kc], bh0, bh1);
                mma16816(sacc[j], ql[kc], bh0, bh1);
                mma16816(sacc[j], qh[kc], bl0, bl1);
            }
        }

        const int ksb = kt * 64;
        float rmx0 = -NEGBIG, rmx1 = -NEGBIG;
        #pragma unroll
        for (int j = 0; j < 8; j++) {
            int k0i = ksb + j * 8 + c * 2;
            if (k0i >= NSUB) sacc[j][0] = -NEGBIG;
            if (k0i + 1 >= NSUB) sacc[j][1] = -NEGBIG;
            if (k0i >= NSUB) sacc[j][2] = -NEGBIG;
            if (k0i + 1 >= NSUB) sacc[j][3] = -NEGBIG;
            rmx0 = fmaxf(rmx0, fmaxf(sacc[j][0], sacc[j][1]));
            rmx1 = fmaxf(rmx1, fmaxf(sacc[j][2], sacc[j][3]));
        }
        rmx0 = fmaxf(rmx0, __shfl_xor_sync(0xffffffffu, rmx0, 1));
        rmx0 = fmaxf(rmx0, __shfl_xor_sync(0xffffffffu, rmx0, 2));
        rmx1 = fmaxf(rmx1, __shfl_xor_sync(0xffffffffu, rmx1, 1));
        rmx1 = fmaxf(rmx1, __shfl_xor_sync(0xffffffffu, rmx1, 2));

        float mn0 = fmaxf(m0, rmx0), mn1 = fmaxf(m1, rmx1);
        float a0 = __expf(m0 - mn0), a1 = __expf(m1 - mn1);
        m0 = mn0; m1 = mn1;
        float s0 = 0.f, s1 = 0.f;
        #pragma unroll
        for (int j = 0; j < 8; j++) {
            sacc[j][0] = __expf(sacc[j][0] - mn0);
            sacc[j][1] = __expf(sacc[j][1] - mn0);
            sacc[j][2] = __expf(sacc[j][2] - mn1);
            sacc[j][3] = __expf(sacc[j][3] - mn1);
            s0 += sacc[j][0] + sacc[j][1];
            s1 += sacc[j][2] + sacc[j][3];
        }
        s0 += __shfl_xor_sync(0xffffffffu, s0, 1);
        s0 += __shfl_xor_sync(0xffffffffu, s0, 2);
        s1 += __shfl_xor_sync(0xffffffffu, s1, 1);
        s1 += __shfl_xor_sync(0xffffffffu, s1, 2);
        l0 = l0 * a0 + s0;
        l1 = l1 * a1 + s1;
        #pragma unroll
        for (int j = 0; j < 8; j++) {
            oacc[j][0] *= a0; oacc[j][1] *= a0;
            oacc[j][2] *= a1; oacc[j][3] *= a1;
        }

        #pragma unroll
        for (int kc = 0; kc < 4; kc++) {
            int j0 = 2 * kc, j1 = 2 * kc + 1;
            uint32_t pah[4], pal[4];
            {
                uint32_t h;
                h = packbf(sacc[j0][1], sacc[j0][0]); pah[0] = h;
                pal[0] = packbf(sacc[j0][1] - __uint_as_float(h & 0xffff0000u),
                                sacc[j0][0] - __uint_as_float(h << 16));
                h = packbf(sacc[j0][3], sacc[j0][2]); pah[1] = h;
                pal[1] = packbf(sacc[j0][3] - __uint_as_float(h & 0xffff0000u),
                                sacc[j0][2] - __uint_as_float(h << 16));
                h = packbf(sacc[j1][1], sacc[j1][0]); pah[2] = h;
                pal[2] = packbf(sacc[j1][1] - __uint_as_float(h & 0xffff0000u),
                                sacc[j1][0] - __uint_as_float(h << 16));
                h = packbf(sacc[j1][3], sacc[j1][2]); pah[3] = h;
                pal[3] = packbf(sacc[j1][3] - __uint_as_float(h & 0xffff0000u),
                                sacc[j1][2] - __uint_as_float(h << 16));
            }
            #pragma unroll
            for (int j = 0; j < 8; j++) {
                int dvrow = j * 8 + lq;
                int kk0 = kc * 16 + c * 2;
                uint32_t bh0 = *(const uint32_t*)(VThS + dvrow * SK + kk0);
                uint32_t bh1 = *(const uint32_t*)(VThS + dvrow * SK + kk0 + 8);
                uint32_t bl0 = *(const uint32_t*)(VTlS + dvrow * SK + kk0);
                uint32_t bl1 = *(const uint32_t*)(VTlS + dvrow * SK + kk0 + 8);
                mma16816(oacc[j], pah, bh0, bh1);
                mma16816(oacc[j], pal, bh0, bh1);
                mma16816(oacc[j], pah, bl0, bl1);
            }
        }
    }

    // ---- band pass ----
    __syncthreads();
    float* Kband = (float*)(buf);
    float* Vband = Kband + 134 * BSW;
    for (int i = tid; i < 134 * 64; i += 256) {
        int rr = i >> 6, d = i & 63;
        int g = q0 - 3 + rr;
        float kv = 0.f, vv = 0.f;
        if (g >= 0) {
            size_t o = gq + (size_t)g * 64 + d;
            kv = __bfloat162float(g_Kh[o]) + __bfloat162float(g_Kl[o]);
            vv = g_Vf[o];
        }
        Kband[rr * BSW + d] = kv;
        Vband[rr * BSW + d] = vv;
    }
    __syncthreads();

    float bl[2][2];
    #pragma unroll
    for (int rh = 0; rh < 2; rh++) {
        int qlcl = w * 16 + lq + 8 * rh;
        int kk0 = c, kk1 = c + 4;
        float acc0 = 0.f, acc1 = 0.f;
        const float* kb0 = Kband + (qlcl + kk0) * BSW;
        const float* kb1 = Kband + (qlcl + kk1) * BSW;
        #pragma unroll 8
        for (int d = 0; d < 64; d++) {
            float qf = __bfloat162float(QhS[qlcl * SK + d]) + __bfloat162float(QlS[qlcl * SK + d]);
            acc0 += qf * kb0[d];
            if (kk1 < 7) acc1 += qf * kb1[d];
        }
        bl[rh][0] = acc0;
        bl[rh][1] = (kk1 < 7) ? acc1 : -NEGBIG;
    }

    {
        float rmx0 = fmaxf(bl[0][0], bl[0][1]);
        float rmx1 = fmaxf(bl[1][0], bl[1][1]);
        rmx0 = fmaxf(rmx0, __shfl_xor_sync(0xffffffffu, rmx0, 1));
        rmx0 = fmaxf(rmx0, __shfl_xor_sync(0xffffffffu, rmx0, 2));
        rmx1 = fmaxf(rmx1, __shfl_xor_sync(0xffffffffu, rmx1, 1));
        rmx1 = fmaxf(rmx1, __shfl_xor_sync(0xffffffffu, rmx1, 2));
        float mn0 = fmaxf(m0, rmx0), mn1 = fmaxf(m1, rmx1);
        float a0 = __expf(m0 - mn0), a1 = __expf(m1 - mn1);
        m0 = mn0; m1 = mn1;
        float p00 = __expf(bl[0][0] - mn0);
        float p01 = (c + 4 < 7) ? __expf(bl[0][1] - mn0) : 0.f;
        float p10 = __expf(bl[1][0] - mn1);
        float p11 = (c + 4 < 7) ? __expf(bl[1][1] - mn1) : 0.f;
        float s0 = p00 + p01, s1 = p10 + p11;
        s0 += __shfl_xor_sync(0xffffffffu, s0, 1);
        s0 += __shfl_xor_sync(0xffffffffu, s0, 2);
        s1 += __shfl_xor_sync(0xffffffffu, s1, 1);
        s1 += __shfl_xor_sync(0xffffffffu, s1, 2);
        l0 = l0 * a0 + s0;
        l1 = l1 * a1 + s1;
        #pragma unroll
        for (int j = 0; j < 8; j++) {
            oacc[j][0] *= a0; oacc[j][1] *= a0;
            oacc[j][2] *= a1; oacc[j][3] *= a1;
        }

        int r0 = w * 16 + lq;
        #pragma unroll
        for (int kk = 0; kk < 7; kk++) {
            int src = (l & ~3) | (kk & 3);
            float pb0 = __shfl_sync(0xffffffffu, (kk < 4) ? p00 : p01, src);
            float pb1 = __shfl_sync(0xffffffffu, (kk < 4) ? p10 : p11, src);
            const float* v0 = Vband + (r0 + kk) * BSW + c * 2;
            const float* v1 = Vband + (r0 + 8 + kk) * BSW + c * 2;
            #pragma unroll
            for (int j = 0; j < 8; j++) {
                float2 a = *(const float2*)(v0 + j * 8);
                float2 bq = *(const float2*)(v1 + j * 8);
                oacc[j][0] += pb0 * a.x; oacc[j][1] += pb0 * a.y;
                oacc[j][2] += pb1 * bq.x; oacc[j][3] += pb1 * bq.y;
            }
        }
    }

    const int b = combo >> 5;
    const int h = (combo >> 2) & 7;
    const int r = combo & 3;
    float inv0 = 1.f / l0, inv1 = 1.f / l1;
    int qg = q0 + w * 16 + lq;
    size_t o0 = ((size_t)(b * SEQL + qg * 4 + r)) * OUTD + h * 64 + c * 2;
    size_t o1 = ((size_t)(b * SEQL + (qg + 8) * 4 + r)) * OUTD + h * 64 + c * 2;
    #pragma unroll
    for (int j = 0; j < 8; j++) {
        *(float2*)(out + o0 + j * 8) = make_float2(oacc[j][0] * inv0, oacc[j][1] * inv0);
        *(float2*)(out + o1 + j * 8) = make_float2(oacc[j][2] * inv1, oacc[j][3] * inv1);
    }
}

// ---------------------------------------------------------------------------
extern "C" void kernel_launch(void* const* d_in, const int* in_sizes, int n_in,
                              void* d_out, int out_size)
{
    const float* x  = (const float*)d_in[0];
    const float* Wq = (const float*)d_in[1];
    const float* Wk = (const float*)d_in[2];
    const float* Wv = (const float*)d_in[3];
    float* out = (float*)d_out;

    cudaFuncSetAttribute(attn_kernel, cudaFuncAttributeMaxDynamicSharedMemorySize, SMEM_BYTES);
    cudaFuncSetAttribute(proj_tc_kernel, cudaFuncAttributeMaxDynamicSharedMemorySize,
                         P_SMEM_ELEMS * 2);

    splitx_kernel<<<(BATCH * SEQL * OUTD / 4) / 256, 256>>>(x);
    splitw_kernel<<<dim3(OUTD, 3), 256>>>(Wq, Wk, Wv);

    dim3 pgrid(MXP / 128, NHEAD, 3);            // 65 x 8 x 3
    proj_tc_kernel<<<pgrid, 256, P_SMEM_ELEMS * 2>>>(out);

    dim3 agrid(SEQL / RATE / BQ, NCOMBO);       // 8 x 64
    attn_kernel<<<agrid, 256, SMEM_BYTES>>>(out);
}

// round 6
// speedup vs baseline: 2.9512x; 1.0785x over previous
#include <cuda_runtime.h>
#include <cuda_bf16.h>
#include <cstdint>

#define BATCH 2
#define SEQL  4096
#define OUTD  512
#define NHEAD 8
#define RATE  4
#define NSUB  1025
#define NSUBP 1088
#define NCOMBO 64
#define SCALE 0.125f
#define LOG2E 1.44269504088896340736f
#define NEGBIG 1e30f

#define MPB   4160
#define MXP   (2 * MPB)     // 8320 = 65 * 128

#define BQ 128
#define SK 72
#define BSW 68

typedef __nv_bfloat16 bf16;

// attention scratch (zero-init; pad keys >= 1024 stay zero forever)
__device__ bf16 g_Qh[(size_t)NCOMBO * NSUBP * 64];
__device__ bf16 g_Ql[(size_t)NCOMBO * NSUBP * 64];
__device__ bf16 g_Kh[(size_t)NCOMBO * NSUBP * 64];
__device__ bf16 g_Kl[(size_t)NCOMBO * NSUBP * 64];
__device__ bf16 g_VTh[(size_t)NCOMBO * 64 * NSUBP];
__device__ bf16 g_VTl[(size_t)NCOMBO * 64 * NSUBP];
__device__ float g_Vf[(size_t)NCOMBO * NSUBP * 64];
__device__ bf16 g_xh[(size_t)MXP * OUTD];
__device__ bf16 g_xl[(size_t)MXP * OUTD];
__device__ bf16 g_WhT[3][OUTD * OUTD];
__device__ bf16 g_WlT[3][OUTD * OUTD];

__device__ __forceinline__ uint32_t packbf(float hi, float lo) {
    uint32_t r; asm("cvt.rn.bf16x2.f32 %0, %1, %2;" : "=r"(r) : "f"(hi), "f"(lo)); return r;
}
__device__ __forceinline__ void cpasync16(uint32_t s, const void* g) {
    asm volatile("cp.async.cg.shared.global [%0], [%1], 16;\n" :: "r"(s), "l"(g));
}
__device__ __forceinline__ void cpcommit() { asm volatile("cp.async.commit_group;\n"); }
__device__ __forceinline__ void cpwait0()  { asm volatile("cp.async.wait_group 0;\n"); }
__device__ __forceinline__ void cpwait1()  { asm volatile("cp.async.wait_group 1;\n"); }

__device__ __forceinline__ void mma16816(float* d, const uint32_t* a, uint32_t b0, uint32_t b1) {
    asm volatile("mma.sync.aligned.m16n8k16.row.col.f32.bf16.bf16.f32 "
        "{%0,%1,%2,%3}, {%4,%5,%6,%7}, {%8,%9}, {%0,%1,%2,%3};"
        : "+f"(d[0]), "+f"(d[1]), "+f"(d[2]), "+f"(d[3])
        : "r"(a[0]), "r"(a[1]), "r"(a[2]), "r"(a[3]), "r"(b0), "r"(b1));
}

// ---------------------------------------------------------------------------
__global__ __launch_bounds__(256) void splitx_kernel(const float* __restrict__ x)
{
    int idx = blockIdx.x * 256 + threadIdx.x;
    int flat = idx * 4;
    int b = flat / (SEQL * OUTD);
    int rem = flat - b * (SEQL * OUTD);
    int t = rem / OUTD;
    int k = rem - t * OUTD;
    float4 v = *(const float4*)(x + (size_t)flat);
    size_t o = ((size_t)(b * MPB + t)) * OUTD + k;
    float hx = __bfloat162float(__float2bfloat16(v.x));
    float hy = __bfloat162float(__float2bfloat16(v.y));
    float hz = __bfloat162float(__float2bfloat16(v.z));
    float hw = __bfloat162float(__float2bfloat16(v.w));
    *(uint2*)(g_xh + o) = make_uint2(packbf(hy, hx), packbf(hw, hz));
    *(uint2*)(g_xl + o) = make_uint2(packbf(v.y - hy, v.x - hx), packbf(v.w - hw, v.z - hz));
}

__global__ __launch_bounds__(256) void splitw_kernel(
    const float* __restrict__ Wq, const float* __restrict__ Wk, const float* __restrict__ Wv)
{
    int k = blockIdx.x, z = blockIdx.y;
    const float* W = (z == 0) ? Wq : (z == 1) ? Wk : Wv;
    #pragma unroll
    for (int half = 0; half < 2; half++) {
        int n = threadIdx.x + half * 256;
        float v = W[(size_t)k * OUTD + n];
        bf16 h = __float2bfloat16(v);
        g_WhT[z][(size_t)n * OUTD + k] = h;
        g_WlT[z][(size_t)n * OUTD + k] = __float2bfloat16(v - __bfloat162float(h));
    }
}

// ---------------------------------------------------------------------------
// Tensor-core projection. z==2 gets a transposed-C epilogue for coalesced VT.
// ---------------------------------------------------------------------------
#define KT 32
#define SA 40
#define P_AH 0
#define P_AL (2 * 128 * SA)
#define P_BH (4 * 128 * SA)
#define P_BL (P_BH + 2 * 64 * SA)
#define P_STAGE_ELEMS (P_BL + 2 * 64 * SA)       // 30720 bf16 = 61440 B
#define SC 68
#define SCT 132
// epilogue floats: C (128*SC = 8704) + CT (64*SCT = 8448) = 17152 fl = 68608 B
#define P_SMEM_BYTES 69632

__global__ __launch_bounds__(256, 2) void proj_tc_kernel()
{
    extern __shared__ __align__(16) bf16 psm[];
    const int tid = threadIdx.x;
    const int w = tid >> 5, l = tid & 31;
    const int lq = l >> 2, c = l & 3;
    const int wm = w & 3, wn = w >> 2;
    const int m0 = blockIdx.x * 128;
    const int n0 = blockIdx.y * 64;
    const int z  = blockIdx.z;
    const uint32_t su = (uint32_t)__cvta_generic_to_shared(psm);

    const bf16* WhT = g_WhT[z] + (size_t)n0 * OUTD;
    const bf16* WlT = g_WlT[z] + (size_t)n0 * OUTD;

    auto stage = [&](int kt, int bi) {
        const int k0 = kt * KT;
        #pragma unroll
        for (int it = 0; it < 4; it++) {
            int cid = tid + it * 256;
            int sp = cid >> 9, rem = cid & 511;
            int row = rem >> 2, seg = rem & 3;
            uint32_t dst = su + (uint32_t)(((sp ? P_AL : P_AH) + bi * 128 * SA + row * SA + seg * 8) * 2);
            const bf16* src = (sp ? g_xl : g_xh) + (size_t)(m0 + row) * OUTD + k0 + seg * 8;
            cpasync16(dst, src);
        }
        #pragma unroll
        for (int it = 0; it < 2; it++) {
            int cid = tid + it * 256;
            int sp = cid >> 8, rem = cid & 255;
            int row = rem >> 2, seg = rem & 3;
            uint32_t dst = su + (uint32_t)(((sp ? P_BL : P_BH) + bi * 64 * SA + row * SA + seg * 8) * 2);
            const bf16* src = (sp ? WlT : WhT) + (size_t)row * OUTD + k0 + seg * 8;
            cpasync16(dst, src);
        }
        cpcommit();
    };

    stage(0, 0);

    float acc[2][4][4];
    #pragma unroll
    for (int i = 0; i < 2; i++)
        #pragma unroll
        for (int j = 0; j < 4; j++)
            #pragma unroll
            for (int t = 0; t < 4; t++) acc[i][j][t] = 0.f;

    for (int kt = 0; kt < OUTD / KT; kt++) {
        if (kt < OUTD / KT - 1) { stage(kt + 1, (kt + 1) & 1); cpwait1(); }
        else cpwait0();
        __syncthreads();
        const bf16* Ah = psm + P_AH + (kt & 1) * 128 * SA;
        const bf16* Al = psm + P_AL + (kt & 1) * 128 * SA;
        const bf16* Bh = psm + P_BH + (kt & 1) * 64 * SA;
        const bf16* Bl = psm + P_BL + (kt & 1) * 64 * SA;

        #pragma unroll
        for (int hh = 0; hh < 2; hh++) {
            const int kb = hh * 16;
            uint32_t ah[2][4], al[2][4];
            #pragma unroll
            for (int mb = 0; mb < 2; mb++) {
                int r0 = wm * 32 + mb * 16 + lq;
                ah[mb][0] = *(const uint32_t*)(Ah + r0 * SA + kb + c * 2);
                ah[mb][1] = *(const uint32_t*)(Ah + (r0 + 8) * SA + kb + c * 2);
                ah[mb][2] = *(const uint32_t*)(Ah + r0 * SA + kb + c * 2 + 8);
                ah[mb][3] = *(const uint32_t*)(Ah + (r0 + 8) * SA + kb + c * 2 + 8);
                al[mb][0] = *(const uint32_t*)(Al + r0 * SA + kb + c * 2);
                al[mb][1] = *(const uint32_t*)(Al + (r0 + 8) * SA + kb + c * 2);
                al[mb][2] = *(const uint32_t*)(Al + r0 * SA + kb + c * 2 + 8);
                al[mb][3] = *(const uint32_t*)(Al + (r0 + 8) * SA + kb + c * 2 + 8);
            }
            #pragma unroll
            for (int nb = 0; nb < 4; nb++) {
                int n = wn * 32 + nb * 8 + lq;
                uint32_t bh0 = *(const uint32_t*)(Bh + n * SA + kb + c * 2);
                uint32_t bh1 = *(const uint32_t*)(Bh + n * SA + kb + c * 2 + 8);
                uint32_t bl0 = *(const uint32_t*)(Bl + n * SA + kb + c * 2);
                uint32_t bl1 = *(const uint32_t*)(Bl + n * SA + kb + c * 2 + 8);
                #pragma unroll
                for (int mb = 0; mb < 2; mb++) {
                    mma16816(acc[mb][nb], ah[mb], bh0, bh1);
                    mma16816(acc[mb][nb], al[mb], bh0, bh1);
                    mma16816(acc[mb][nb], ah[mb], bl0, bl1);
                }
            }
        }
        __syncthreads();
    }

    // Stage C (row-major) and, for z==2, also C_T (transposed).
    float* C  = (float*)psm;
    float* CT = C + 128 * SC;
    #pragma unroll
    for (int mb = 0; mb < 2; mb++) {
        int r0 = wm * 32 + mb * 16 + lq;
        #pragma unroll
        for (int nb = 0; nb < 4; nb++) {
            int col = wn * 32 + nb * 8 + c * 2;
            *(float2*)(C + r0 * SC + col)       = make_float2(acc[mb][nb][0], acc[mb][nb][1]);
            *(float2*)(C + (r0 + 8) * SC + col) = make_float2(acc[mb][nb][2], acc[mb][nb][3]);
            if (z == 2) {
                CT[col * SCT + r0]           = acc[mb][nb][0];
                CT[(col + 1) * SCT + r0]     = acc[mb][nb][1];
                CT[col * SCT + r0 + 8]       = acc[mb][nb][2];
                CT[(col + 1) * SCT + r0 + 8] = acc[mb][nb][3];
            }
        }
    }
    __syncthreads();

    const int h = blockIdx.y;
    const int bb = m0 / MPB;
    const int t0 = m0 - bb * MPB;
    const bool fast = ((m0 + 127) / MPB == bb) && (t0 + 128 <= SEQL);

    if (z == 2 && fast) {
        const int iq0 = t0 >> 2;
        // g_Vf: coalesced row-major (2 threads/row, float4)
        {
            int r = tid >> 1, half = tid & 1;
            int t = t0 + r;
            int iq = t >> 2, r4 = t & 3;
            int combo = (bb * NHEAD + h) * RATE + r4;
            size_t orow = ((size_t)combo * NSUBP + iq) * 64 + half * 32;
            #pragma unroll
            for (int j = 0; j < 8; j++)
                *(float4*)(g_Vf + orow + j * 4) = *(const float4*)(C + r * SC + half * 32 + j * 4);
        }
        // g_VTh/g_VTl: transposed, 8B-contiguous along iq
        int g = tid & 7, r4 = (tid >> 3) & 3, dl = tid >> 5;
        int combo = (bb * NHEAD + h) * RATE + r4;
        #pragma unroll
        for (int it = 0; it < 8; it++) {
            int d = it * 8 + dl;
            float v[4], hi[4];
            #pragma unroll
            for (int j = 0; j < 4; j++) {
                int r = (g * 4 + j) * 4 + r4;
                v[j] = CT[d * SCT + r];
                hi[j] = __bfloat162float(__float2bfloat16(v[j]));
            }
            uint2 uh = make_uint2(packbf(hi[1], hi[0]), packbf(hi[3], hi[2]));
            uint2 ul = make_uint2(packbf(v[1] - hi[1], v[0] - hi[0]),
                                  packbf(v[3] - hi[3], v[2] - hi[2]));
            size_t o = ((size_t)combo * 64 + d) * NSUBP + iq0 + g * 4;
            *(uint2*)(g_VTh + o) = uh;
            *(uint2*)(g_VTl + o) = ul;
        }
    } else {
        // generic per-row epilogue
        int r = tid >> 1, half = tid & 1;
        int m = m0 + r;
        int b = m / MPB;
        int t = m - b * MPB;
        if (t < SEQL) {
            int iq = t >> 2, r4 = t & 3;
            int combo = (b * NHEAD + h) * RATE + r4;
            size_t orow = ((size_t)combo * NSUBP + iq) * 64;
            #pragma unroll
            for (int j = 0; j < 8; j++) {
                int d = half * 32 + j * 4;
                float4 v = *(const float4*)(C + r * SC + d);
                float vf[4] = {v.x, v.y, v.z, v.w};
                if (z == 0) {
                    #pragma unroll
                    for (int e = 0; e < 4; e++) vf[e] *= SCALE * LOG2E;
                }
                float h0 = __bfloat162float(__float2bfloat16(vf[0]));
                float h1 = __bfloat162float(__float2bfloat16(vf[1]));
                float h2 = __bfloat162float(__float2bfloat16(vf[2]));
                float h3 = __bfloat162float(__float2bfloat16(vf[3]));
                uint2 uh = make_uint2(packbf(h1, h0), packbf(h3, h2));
                uint2 ul = make_uint2(packbf(vf[1] - h1, vf[0] - h0), packbf(vf[3] - h3, vf[2] - h2));
                if (z == 0) {
                    *(uint2*)(g_Qh + orow + d) = uh;
                    *(uint2*)(g_Ql + orow + d) = ul;
                } else if (z == 1) {
                    *(uint2*)(g_Kh + orow + d) = uh;
                    *(uint2*)(g_Kl + orow + d) = ul;
                } else {
                    *(float4*)(g_Vf + orow + d) = v;
                    float hs[4] = {h0, h1, h2, h3};
                    #pragma unroll
                    for (int e = 0; e < 4; e++) {
                        size_t ot = ((size_t)combo * 64 + d + e) * NSUBP + iq;
                        g_VTh[ot] = __float2bfloat16(hs[e]);
                        g_VTl[ot] = __float2bfloat16(vf[e] - hs[e]);
                    }
                }
            }
        }
    }
}

// ---------------------------------------------------------------------------
// Flash attention: 16 unmasked key tiles (0..1023), analytic zero-key, band.
// ---------------------------------------------------------------------------
#define SM_QH 0
#define SM_QL (BQ * SK)
#define SM_BUF (2 * BQ * SK)
#define BUF_SZ (4 * 64 * SK)
#define SMEM_BYTES ((SM_BUF + 2 * BUF_SZ) * 2)   // 110592

__global__ __launch_bounds__(256, 2) void attn_kernel(float* __restrict__ out)
{
    extern __shared__ __align__(16) bf16 sm[];
    bf16* QhS = sm + SM_QH;
    bf16* QlS = sm + SM_QL;
    bf16* buf = sm + SM_BUF;

    const int tid = threadIdx.x;
    const int w = tid >> 5, l = tid & 31;
    const int lq = l >> 2;
    const int c  = l & 3;
    const int combo = blockIdx.y;
    const int q0 = blockIdx.x * BQ;
    const uint32_t smem_u32 = (uint32_t)__cvta_generic_to_shared(sm);

    const size_t gq = (size_t)combo * NSUBP * 64;
    const size_t gvt = (size_t)combo * 64 * NSUBP;

    #pragma unroll
    for (int it = 0; it < 8; it++) {
        int cid = tid + it * 256;
        int arr = cid >> 10;
        int rem = cid & 1023;
        int row = rem >> 3, seg = rem & 7;
        uint32_t dst = smem_u32 + (uint32_t)(((arr ? SM_QL : SM_QH) + row * SK) * 2 + seg * 16);
        const bf16* src = (arr ? g_Ql : g_Qh) + gq + (size_t)(q0 + row) * 64 + seg * 8;
        cpasync16(dst, src);
    }
    cpcommit();

    {
        #pragma unroll
        for (int it = 0; it < 8; it++) {
            int cid = tid + it * 256;
            int arr = cid >> 9;
            int rem = cid & 511;
            int row = rem >> 3, seg = rem & 7;
            uint32_t dst = smem_u32 + (uint32_t)((SM_BUF + arr * 64 * SK + row * SK) * 2 + seg * 16);
            const bf16* src;
            if (arr == 0)      src = g_Kh + gq + (size_t)row * 64 + seg * 8;
            else if (arr == 1) src = g_Kl + gq + (size_t)row * 64 + seg * 8;
            else if (arr == 2) src = g_VTh + gvt + (size_t)row * NSUBP + seg * 8;
            else               src = g_VTl + gvt + (size_t)row * NSUBP + seg * 8;
            cpasync16(dst, src);
        }
        cpcommit();
    }
    cpwait0();
    __syncthreads();

    uint32_t qh[4][4], ql[4][4];
    {
        int r0 = w * 16 + lq;
        #pragma unroll
        for (int kc = 0; kc < 4; kc++) {
            int d0 = kc * 16 + c * 2;
            qh[kc][0] = *(const uint32_t*)(QhS + r0 * SK + d0);
            qh[kc][1] = *(const uint32_t*)(QhS + (r0 + 8) * SK + d0);
            qh[kc][2] = *(const uint32_t*)(QhS + r0 * SK + d0 + 8);
            qh[kc][3] = *(const uint32_t*)(QhS + (r0 + 8) * SK + d0 + 8);
            ql[kc][0] = *(const uint32_t*)(QlS + r0 * SK + d0);
            ql[kc][1] = *(const uint32_t*)(QlS + (r0 + 8) * SK + d0);
            ql[kc][2] = *(const uint32_t*)(QlS + r0 * SK + d0 + 8);
            ql[kc][3] = *(const uint32_t*)(QlS + (r0 + 8) * SK + d0 + 8);
        }
    }

    float oacc[8][4];
    #pragma unroll
    for (int j = 0; j < 8; j++)
        #pragma unroll
        for (int t = 0; t < 4; t++) oacc[j][t] = 0.f;
    float m0 = -NEGBIG, m1 = -NEGBIG, l0 = 0.f, l1 = 0.f;

    for (int kt = 0; kt < 16; kt++) {
        __syncthreads();
        if (kt < 15) {
            const int ks = (kt + 1) * 64;
            const int boff = SM_BUF + ((kt + 1) & 1) * BUF_SZ;
            #pragma unroll
            for (int it = 0; it < 8; it++) {
                int cid = tid + it * 256;
                int arr = cid >> 9;
                int rem = cid & 511;
                int row = rem >> 3, seg = rem & 7;
                uint32_t dst = smem_u32 + (uint32_t)((boff + arr * 64 * SK + row * SK) * 2 + seg * 16);
                const bf16* src;
                if (arr == 0)      src = g_Kh + gq + (size_t)(ks + row) * 64 + seg * 8;
                else if (arr == 1) src = g_Kl + gq + (size_t)(ks + row) * 64 + seg * 8;
                else if (arr == 2) src = g_VTh + gvt + (size_t)row * NSUBP + ks + seg * 8;
                else               src = g_VTl + gvt + (size_t)row * NSUBP + ks + seg * 8;
                cpasync16(dst, src);
            }
            cpcommit();
            cpwait1();
        } else {
            cpwait0();
        }
        __syncthreads();

        const bf16* KhS  = buf + (kt & 1) * BUF_SZ;
        const bf16* KlS  = KhS + 64 * SK;
        const bf16* VThS = KhS + 2 * 64 * SK;
        const bf16* VTlS = KhS + 3 * 64 * SK;

        float sacc[8][4];
        #pragma unroll
        for (int j = 0; j < 8; j++)
            #pragma unroll
            for (int t = 0; t < 4; t++) sacc[j][t] = 0.f;

        #pragma unroll
        for (int kc = 0; kc < 4; kc++) {
            #pragma unroll
            for (int j = 0; j < 8; j++) {
                int krow = j * 8 + lq;
                int d0 = kc * 16 + c * 2;
                uint32_t bh0 = *(const uint32_t*)(KhS + krow * SK + d0);
                uint32_t bh1 = *(const uint32_t*)(KhS + krow * SK + d0 + 8);
                uint32_t bl0 = *(const uint32_t*)(KlS + krow * SK + d0);
                uint32_t bl1 = *(const uint32_t*)(KlS + krow * SK + d0 + 8);
                mma16816(sacc[j], qh[kc], bh0, bh1);
                mma16816(sacc[j], ql[kc], bh0, bh1);
                mma16816(sacc[j], qh[kc], bl0, bl1);
            }
        }

        // online softmax in exp2 space (no masking: all 1024 keys valid)
        float rmx0 = -NEGBIG, rmx1 = -NEGBIG;
        #pragma unroll
        for (int j = 0; j < 8; j++) {
            rmx0 = fmaxf(rmx0, fmaxf(sacc[j][0], sacc[j][1]));
            rmx1 = fmaxf(rmx1, fmaxf(sacc[j][2], sacc[j][3]));
        }
        rmx0 = fmaxf(rmx0, __shfl_xor_sync(0xffffffffu, rmx0, 1));
        rmx0 = fmaxf(rmx0, __shfl_xor_sync(0xffffffffu, rmx0, 2));
        rmx1 = fmaxf(rmx1, __shfl_xor_sync(0xffffffffu, rmx1, 1));
        rmx1 = fmaxf(rmx1, __shfl_xor_sync(0xffffffffu, rmx1, 2));

        float mn0 = fmaxf(m0, rmx0), mn1 = fmaxf(m1, rmx1);
        float a0 = exp2f(m0 - mn0), a1 = exp2f(m1 - mn1);
        m0 = mn0; m1 = mn1;
        float s0 = 0.f, s1 = 0.f;
        #pragma unroll
        for (int j = 0; j < 8; j++) {
            sacc[j][0] = exp2f(sacc[j][0] - mn0);
            sacc[j][1] = exp2f(sacc[j][1] - mn0);
            sacc[j][2] = exp2f(sacc[j][2] - mn1);
            sacc[j][3] = exp2f(sacc[j][3] - mn1);
            s0 += sacc[j][0] + sacc[j][1];
            s1 += sacc[j][2] + sacc[j][3];
        }
        s0 += __shfl_xor_sync(0xffffffffu, s0, 1);
        s0 += __shfl_xor_sync(0xffffffffu, s0, 2);
        s1 += __shfl_xor_sync(0xffffffffu, s1, 1);
        s1 += __shfl_xor_sync(0xffffffffu, s1, 2);
        l0 = l0 * a0 + s0;
        l1 = l1 * a1 + s1;
        #pragma unroll
        for (int j = 0; j < 8; j++) {
            oacc[j][0] *= a0; oacc[j][1] *= a0;
            oacc[j][2] *= a1; oacc[j][3] *= a1;
        }

        #pragma unroll
        for (int kc = 0; kc < 4; kc++) {
            int j0 = 2 * kc, j1 = 2 * kc + 1;
            uint32_t pah[4], pal[4];
            {
                uint32_t h;
                h = packbf(sacc[j0][1], sacc[j0][0]); pah[0] = h;
                pal[0] = packbf(sacc[j0][1] - __uint_as_float(h & 0xffff0000u),
                                sacc[j0][0] - __uint_as_float(h << 16));
                h = packbf(sacc[j0][3], sacc[j0][2]); pah[1] = h;
                pal[1] = packbf(sacc[j0][3] - __uint_as_float(h & 0xffff0000u),
                                sacc[j0][2] - __uint_as_float(h << 16));
                h = packbf(sacc[j1][1], sacc[j1][0]); pah[2] = h;
                pal[2] = packbf(sacc[j1][1] - __uint_as_float(h & 0xffff0000u),
                                sacc[j1][0] - __uint_as_float(h << 16));
                h = packbf(sacc[j1][3], sacc[j1][2]); pah[3] = h;
                pal[3] = packbf(sacc[j1][3] - __uint_as_float(h & 0xffff0000u),
                                sacc[j1][2] - __uint_as_float(h << 16));
            }
            #pragma unroll
            for (int j = 0; j < 8; j++) {
                int dvrow = j * 8 + lq;
                int kk0 = kc * 16 + c * 2;
                uint32_t bh0 = *(const uint32_t*)(VThS + dvrow * SK + kk0);
                uint32_t bh1 = *(const uint32_t*)(VThS + dvrow * SK + kk0 + 8);
                uint32_t bl0 = *(const uint32_t*)(VTlS + dvrow * SK + kk0);
                uint32_t bl1 = *(const uint32_t*)(VTlS + dvrow * SK + kk0 + 8);
                mma16816(oacc[j], pah, bh0, bh1);
                mma16816(oacc[j], pal, bh0, bh1);
                mma16816(oacc[j], pah, bl0, bl1);
            }
        }
    }

    // ---- band pass (7 banded logits) + analytic zero key (logit 0) ----
    __syncthreads();
    float* Kband = (float*)(buf);
    float* Vband = Kband + 134 * BSW;
    for (int i = tid; i < 134 * 64; i += 256) {
        int rr = i >> 6, d = i & 63;
        int g = q0 - 3 + rr;
        float kv = 0.f, vv = 0.f;
        if (g >= 0) {
            size_t o = gq + (size_t)g * 64 + d;
            kv = __bfloat162float(g_Kh[o]) + __bfloat162float(g_Kl[o]);
            vv = g_Vf[o];
        }
        Kband[rr * BSW + d] = kv;
        Vband[rr * BSW + d] = vv;
    }
    __syncthreads();

    float bl[2][2];
    #pragma unroll
    for (int rh = 0; rh < 2; rh++) {
        int qlcl = w * 16 + lq + 8 * rh;
        int kk0 = c, kk1 = c + 4;
        float acc0 = 0.f, acc1 = 0.f;
        const float* kb0 = Kband + (qlcl + kk0) * BSW;
        const float* kb1 = Kband + (qlcl + kk1) * BSW;
        #pragma unroll 8
        for (int d = 0; d < 64; d++) {
            float qf = __bfloat162float(QhS[qlcl * SK + d]) + __bfloat162float(QlS[qlcl * SK + d]);
            acc0 += qf * kb0[d];
            if (kk1 < 7) acc1 += qf * kb1[d];
        }
        bl[rh][0] = acc0;
        bl[rh][1] = (kk1 < 7) ? acc1 : -NEGBIG;
    }

    {
        float rmx0 = fmaxf(bl[0][0], bl[0][1]);
        float rmx1 = fmaxf(bl[1][0], bl[1][1]);
        rmx0 = fmaxf(rmx0, __shfl_xor_sync(0xffffffffu, rmx0, 1));
        rmx0 = fmaxf(rmx0, __shfl_xor_sync(0xffffffffu, rmx0, 2));
        rmx1 = fmaxf(rmx1, __shfl_xor_sync(0xffffffffu, rmx1, 1));
        rmx1 = fmaxf(rmx1, __shfl_xor_sync(0xffffffffu, rmx1, 2));
        // include the zero pad key's logit (exactly 0) in the running max
        float mn0 = fmaxf(fmaxf(m0, rmx0), 0.f);
        float mn1 = fmaxf(fmaxf(m1, rmx1), 0.f);
        float a0 = exp2f(m0 - mn0), a1 = exp2f(m1 - mn1);
        m0 = mn0; m1 = mn1;
        float p00 = exp2f(bl[0][0] - mn0);
        float p01 = (c + 4 < 7) ? exp2f(bl[0][1] - mn0) : 0.f;
        float p10 = exp2f(bl[1][0] - mn1);
        float p11 = (c + 4 < 7) ? exp2f(bl[1][1] - mn1) : 0.f;
        float s0 = p00 + p01, s1 = p10 + p11;
        s0 += __shfl_xor_sync(0xffffffffu, s0, 1);
        s0 += __shfl_xor_sync(0xffffffffu, s0, 2);
        s1 += __shfl_xor_sync(0xffffffffu, s1, 1);
        s1 += __shfl_xor_sync(0xffffffffu, s1, 2);
        // zero key: +exp2(0 - m) to denominator, nothing to numerator
        l0 = l0 * a0 + s0 + exp2f(-mn0);
        l1 = l1 * a1 + s1 + exp2f(-mn1);
        #pragma unroll
        for (int j = 0; j < 8; j++) {
            oacc[j][0] *= a0; oacc[j][1] *= a0;
            oacc[j][2] *= a1; oacc[j][3] *= a1;
        }

        int r0 = w * 16 + lq;
        #pragma unroll
        for (int kk = 0; kk < 7; kk++) {
            int src = (l & ~3) | (kk & 3);
            float pb0 = __shfl_sync(0xffffffffu, (kk < 4) ? p00 : p01, src);
            float pb1 = __shfl_sync(0xffffffffu, (kk < 4) ? p10 : p11, src);
            const float* v0 = Vband + (r0 + kk) * BSW + c * 2;
            const float* v1 = Vband + (r0 + 8 + kk) * BSW + c * 2;
            #pragma unroll
            for (int j = 0; j < 8; j++) {
                float2 a = *(const float2*)(v0 + j * 8);
                float2 bq = *(const float2*)(v1 + j * 8);
                oacc[j][0] += pb0 * a.x; oacc[j][1] += pb0 * a.y;
                oacc[j][2] += pb1 * bq.x; oacc[j][3] += pb1 * bq.y;
            }
        }
    }

    const int b = combo >> 5;
    const int h = (combo >> 2) & 7;
    const int r = combo & 3;
    float inv0 = 1.f / l0, inv1 = 1.f / l1;
    int qg = q0 + w * 16 + lq;
    size_t o0 = ((size_t)(b * SEQL + qg * 4 + r)) * OUTD + h * 64 + c * 2;
    size_t o1 = ((size_t)(b * SEQL + (qg + 8) * 4 + r)) * OUTD + h * 64 + c * 2;
    #pragma unroll
    for (int j = 0; j < 8; j++) {
        *(float2*)(out + o0 + j * 8) = make_float2(oacc[j][0] * inv0, oacc[j][1] * inv0);
        *(float2*)(out + o1 + j * 8) = make_float2(oacc[j][2] * inv1, oacc[j][3] * inv1);
    }
}

// ---------------------------------------------------------------------------
extern "C" void kernel_launch(void* const* d_in, const int* in_sizes, int n_in,
                              void* d_out, int out_size)
{
    const float* x  = (const float*)d_in[0];
    const float* Wq = (const float*)d_in[1];
    const float* Wk = (const float*)d_in[2];
    const float* Wv = (const float*)d_in[3];
    float* out = (float*)d_out;

    cudaFuncSetAttribute(attn_kernel, cudaFuncAttributeMaxDynamicSharedMemorySize, SMEM_BYTES);
    cudaFuncSetAttribute(proj_tc_kernel, cudaFuncAttributeMaxDynamicSharedMemorySize, P_SMEM_BYTES);

    splitx_kernel<<<(BATCH * SEQL * OUTD / 4) / 256, 256>>>(x);
    splitw_kernel<<<dim3(OUTD, 3), 256>>>(Wq, Wk, Wv);

    dim3 pgrid(MXP / 128, NHEAD, 3);
    proj_tc_kernel<<<pgrid, 256, P_SMEM_BYTES>>>();

    dim3 agrid(SEQL / RATE / BQ, NCOMBO);
    attn_kernel<<<agrid, 256, SMEM_BYTES>>>(out);
}